// round 14
// baseline (speedup 1.0000x reference)
#include <cuda_runtime.h>
#include <cuda_fp16.h>
#include <cstdint>

#define N_NODES 50000
#define N_EDGES 800000
#define D_IN 96
#define HID 128
#define SCAN_TPB 1024
#define SCAN_BLOCKS ((N_NODES + SCAN_TPB - 1) / SCAN_TPB)   // 49
#define HALF_OFF (N_NODES * HID)

// ---------------- PDL helpers ----------------
__device__ __forceinline__ void pdl_trigger() {
#if __CUDA_ARCH__ >= 900
    asm volatile("griddepcontrol.launch_dependents;");
#endif
}
__device__ __forceinline__ void pdl_wait() {
#if __CUDA_ARCH__ >= 900
    asm volatile("griddepcontrol.wait;" ::: "memory");
#endif
}

// ---------------- scratch ----------------
__device__ __align__(16) float g_buf0[N_NODES * HID];
__device__ __align__(16) float g_buf1[N_NODES * HID];
__device__ __align__(16) float g_buf2[N_NODES * HID];
__device__ __align__(16) float g_buf3[N_NODES * HID];
__device__ __align__(16) __half g_wt_in[HID * D_IN];
__device__ __align__(16) __half g_wt1[HID * HID];
__device__ __align__(16) __half g_wt2[HID * HID];
__device__ __align__(16) __half g_wtm1a[HID * HID];
__device__ __align__(16) __half g_wtm1b[HID * HID];
__device__ float g_dinv[N_NODES];
__device__ int   g_deg[N_NODES];
__device__ int   g_rowptr[N_NODES + 1];
__device__ int   g_cursor[N_NODES];
__device__ int   g_partials[SCAN_BLOCKS + 1];
__device__ __align__(8) int2 g_csr_sn[N_EDGES];
__device__ __align__(8) int2 g_csr_se[N_EDGES];

// ---------------- graph preprocessing ----------------
__global__ void zero_deg_kernel() {
    int i = blockIdx.x * blockDim.x + threadIdx.x;
    if (i < N_NODES) g_deg[i] = 0;
}

__global__ void hist_kernel(const int* __restrict__ dst) {
    int e = blockIdx.x * blockDim.x + threadIdx.x;
    if (e < N_EDGES) atomicAdd(&g_deg[dst[e]], 1);
}

__global__ void scan1_kernel() {
    __shared__ int ws[32];
    int gid = blockIdx.x * SCAN_TPB + threadIdx.x;
    int lane = threadIdx.x & 31, wid = threadIdx.x >> 5;
    int v = (gid < N_NODES) ? g_deg[gid] : 0;
    if (gid < N_NODES) g_dinv[gid] = rsqrtf((float)(v + 1));
    int x = v;
    #pragma unroll
    for (int off = 1; off < 32; off <<= 1) {
        int t = __shfl_up_sync(0xffffffff, x, off);
        if (lane >= off) x += t;
    }
    if (lane == 31) ws[wid] = x;
    __syncthreads();
    if (wid == 0) {
        int t = ws[lane];
        #pragma unroll
        for (int off = 1; off < 32; off <<= 1) {
            int u = __shfl_up_sync(0xffffffff, t, off);
            if (lane >= off) t += u;
        }
        ws[lane] = t;
    }
    __syncthreads();
    int excl = (wid ? ws[wid - 1] : 0) + x - v;
    if (gid < N_NODES) g_rowptr[gid] = excl;
    if (threadIdx.x == 0) g_partials[blockIdx.x] = ws[31];
}

__global__ void scan2_kernel() {
    int lane = threadIdx.x;
    int v0 = (lane < SCAN_BLOCKS) ? g_partials[lane] : 0;
    int v1 = (lane + 32 < SCAN_BLOCKS) ? g_partials[lane + 32] : 0;
    int x0 = v0;
    #pragma unroll
    for (int off = 1; off < 32; off <<= 1) {
        int t = __shfl_up_sync(0xffffffff, x0, off);
        if (lane >= off) x0 += t;
    }
    int tot0 = __shfl_sync(0xffffffff, x0, 31);
    int x1 = v1;
    #pragma unroll
    for (int off = 1; off < 32; off <<= 1) {
        int t = __shfl_up_sync(0xffffffff, x1, off);
        if (lane >= off) x1 += t;
    }
    if (lane < SCAN_BLOCKS) g_partials[lane] = x0 - v0;
    if (lane + 32 < SCAN_BLOCKS) g_partials[lane + 32] = tot0 + x1 - v1;
    if (lane == 31) g_rowptr[N_NODES] = tot0 + __shfl_sync(0xffffffff, x1, 31);
}

__global__ void scan3_kernel() {
    int gid = blockIdx.x * SCAN_TPB + threadIdx.x;
    if (gid < N_NODES) {
        int r = g_rowptr[gid] + g_partials[blockIdx.x];
        g_rowptr[gid] = r;
        g_cursor[gid] = r;
    }
}

__global__ void fill_kernel(const int* __restrict__ src, const int* __restrict__ dst) {
    int e = blockIdx.x * blockDim.x + threadIdx.x;
    if (e < N_EDGES) {
        int s = src[e], d = dst[e];
        int p = atomicAdd(&g_cursor[d], 1);
        float nm = g_dinv[s] * g_dinv[d];
        g_csr_sn[p] = make_int2(s, __float_as_int(nm));
        g_csr_se[p] = make_int2(s, e);
    }
}

// ---------------- prep: cvt x -> fp16 + all 5 weight transposes ----------------
#define CVT_ELEMS (N_NODES * D_IN / 4)
#define CVT_BLOCKS ((CVT_ELEMS + 255) / 256)
__global__ void prep_kernel(const float* __restrict__ x, __half2* __restrict__ xh,
                            const float* __restrict__ W_in, const float* __restrict__ W1,
                            const float* __restrict__ W2, const float* __restrict__ Wm1,
                            __half* __restrict__ wtin, __half* __restrict__ wt1,
                            __half* __restrict__ wt2, __half* __restrict__ wtm1a,
                            __half* __restrict__ wtm1b) {
    pdl_trigger();
    __shared__ float t[16][17];
    int b = blockIdx.x, tid = threadIdx.x;
    if (b < CVT_BLOCKS) {
        int i = b * 256 + tid;
        if (i < CVT_ELEMS) {
            float4 v = ((const float4*)x)[i];
            xh[i * 2]     = __floats2half2_rn(v.x, v.y);
            xh[i * 2 + 1] = __floats2half2_rn(v.z, v.w);
        }
        return;
    }
    int tb = b - CVT_BLOCKS;
    const float* W; __half* Wt; int K;
    if (tb < 48)       { W = W_in;            Wt = wtin;  K = 96;  }
    else if (tb < 112) { W = W1;              Wt = wt1;   K = 128; tb -= 48; }
    else if (tb < 176) { W = W2;              Wt = wt2;   K = 128; tb -= 112; }
    else if (tb < 240) { W = Wm1;             Wt = wtm1a; K = 128; tb -= 176; }
    else               { W = Wm1 + HID * HID; Wt = wtm1b; K = 128; tb -= 240; }
    int bx = tb % 8, by = tb / 8;
    int tx = tid & 15, ty = tid >> 4;
    int n = bx * 16 + tx, k = by * 16 + ty;
    if (k < K) t[ty][tx] = W[k * 128 + n];
    __syncthreads();
    int n2 = bx * 16 + ty, k2 = by * 16 + tx;
    if (k2 < K) Wt[n2 * K + k2] = __float2half(t[tx][ty]);
}

// ---------------- fp16 mma.sync GEMM machinery ----------------
#define SSTR 56
#define BUF_HALVES (128 * SSTR)
#define BUF_BYTES  (BUF_HALVES * 2)
#define H0STR 136
#define H0_BYTES (128 * H0STR * 2)

__device__ __forceinline__ uint32_t smem_u32(const void* p) {
    uint32_t a;
    asm("{ .reg .u64 t; cvta.to.shared.u64 t, %1; cvt.u32.u64 %0, t; }" : "=r"(a) : "l"(p));
    return a;
}
__device__ __forceinline__ void cp_async16(uint32_t dst, const void* src, int sz) {
    asm volatile("cp.async.ca.shared.global [%0], [%1], 16, %2;"
                 :: "r"(dst), "l"(src), "r"(sz) : "memory");
}
#define CP_COMMIT() asm volatile("cp.async.commit_group;" ::: "memory")
#define CP_WAIT1()  asm volatile("cp.async.wait_group 1;" ::: "memory")
#define CP_WAIT0()  asm volatile("cp.async.wait_group 0;" ::: "memory")

#define LDSM_X4(r0, r1, r2, r3, addr)                                          \
    asm volatile("ldmatrix.sync.aligned.m8n8.x4.shared.b16 {%0,%1,%2,%3}, [%4];" \
        : "=r"(r0), "=r"(r1), "=r"(r2), "=r"(r3) : "r"(addr))

#define MMA_F16(c, a, b)                                                       \
    asm volatile(                                                              \
        "mma.sync.aligned.m16n8k16.row.col.f32.f16.f16.f32 "                   \
        "{%0,%1,%2,%3}, {%4,%5,%6,%7}, {%8,%9}, {%0,%1,%2,%3};"                \
        : "+f"((c)[0]), "+f"((c)[1]), "+f"((c)[2]), "+f"((c)[3])               \
        : "r"((a)[0]), "r"((a)[1]), "r"((a)[2]), "r"((a)[3]),                  \
          "r"((b)[0]), "r"((b)[1]))

// ---------------- fused GEMM: xw1 = (relu(x@W_in+b_in)) @ W1, h0 kept in smem ----------------
__global__ void __launch_bounds__(256, 2) gemm_fused_kernel(
    const __half* __restrict__ Xh,
    const __half* __restrict__ Wt0,
    const float* __restrict__ bias0,
    const __half* __restrict__ Wt1,
    __half* __restrict__ C,
    int M)
{
    pdl_trigger();
    extern __shared__ __half sm[];
    const uint32_t sA = smem_u32(sm);
    const uint32_t sB = sA + 2 * BUF_BYTES;
    const uint32_t sH = sB + 2 * BUF_BYTES;

    const int tid = threadIdx.x;
    const int lane = tid & 31, wid = tid >> 5;
    const int gID = lane >> 2, t4 = lane & 3;
    const int wm = wid & 3, wn = wid >> 2;
    const int m0 = blockIdx.x * 128;

    const int lane15 = lane & 15;
    const uint32_t aOff  = (uint32_t)((wm * 32 + lane15) * SSTR) * 2 + (lane >> 4) * 16;
    const uint32_t aOffH = (uint32_t)((wm * 32 + lane15) * H0STR) * 2 + (lane >> 4) * 16;
    const uint32_t bOff  = (uint32_t)((wn * 64 + ((lane >> 4) * 8) + (lane & 7)) * SSTR) * 2
                         + ((lane >> 3) & 1) * 16;

    float acc[2][8][4];
    #pragma unroll
    for (int mi = 0; mi < 2; mi++)
        #pragma unroll
        for (int ni = 0; ni < 8; ni++)
            #pragma unroll
            for (int j = 0; j < 4; j++) acc[mi][ni][j] = 0.f;

    auto load1 = [&](int c, int buf) {
        int k0 = c * 32;
        #pragma unroll
        for (int i = 0; i < 2; i++) {
            int idx = tid + i * 256;
            int row = idx >> 2, seg = idx & 3;
            int g = m0 + row;
            const __half* srcA = Xh + (long)((g < M) ? g : 0) * 96 + k0 + seg * 8;
            cp_async16(sA + buf * BUF_BYTES + row * (SSTR * 2) + seg * 16, srcA, (g < M) ? 16 : 0);
            const __half* srcB = Wt0 + (long)row * 96 + k0 + seg * 8;
            cp_async16(sB + buf * BUF_BYTES + row * (SSTR * 2) + seg * 16, srcB, 16);
        }
        CP_COMMIT();
    };

    pdl_wait();
    load1(0, 0);
    load1(1, 1);

    #pragma unroll
    for (int c = 0; c < 3; c++) {
        if (c < 2) CP_WAIT1(); else CP_WAIT0();
        __syncthreads();
        const int buf = c & 1;
        const uint32_t aBase = sA + buf * BUF_BYTES;
        const uint32_t bBase = sB + buf * BUF_BYTES;
        #pragma unroll
        for (int ks = 0; ks < 2; ks++) {
            const int kbB = ks * 32;
            uint32_t a[2][4], b[8][2];
            LDSM_X4(a[0][0], a[0][1], a[0][2], a[0][3], aBase + aOff + kbB);
            LDSM_X4(a[1][0], a[1][1], a[1][2], a[1][3], aBase + aOff + 16 * SSTR * 2 + kbB);
            #pragma unroll
            for (int j = 0; j < 4; j++)
                LDSM_X4(b[2 * j][0], b[2 * j][1], b[2 * j + 1][0], b[2 * j + 1][1],
                        bBase + bOff + j * 16 * SSTR * 2 + kbB);
            #pragma unroll
            for (int mi = 0; mi < 2; mi++)
                #pragma unroll
                for (int ni = 0; ni < 8; ni++)
                    MMA_F16(acc[mi][ni], a[mi], b[ni]);
        }
        if (c + 2 < 3) {
            __syncthreads();
            load1(c + 2, buf);
        }
    }

    // stage-1 epilogue: bias + relu, h0 tile -> smem
    #pragma unroll
    for (int mi = 0; mi < 2; mi++) {
        int r = wm * 32 + mi * 16 + gID;
        #pragma unroll
        for (int ni = 0; ni < 8; ni++) {
            int col = wn * 64 + ni * 8 + t4 * 2;
            float bx = bias0[col], by = bias0[col + 1];
            __half2 v0 = __floats2half2_rn(fmaxf(acc[mi][ni][0] + bx, 0.f),
                                           fmaxf(acc[mi][ni][1] + by, 0.f));
            __half2 v1 = __floats2half2_rn(fmaxf(acc[mi][ni][2] + bx, 0.f),
                                           fmaxf(acc[mi][ni][3] + by, 0.f));
            *(__half2*)((char*)sm + 4 * BUF_BYTES + (r * H0STR + col) * 2)       = v0;
            *(__half2*)((char*)sm + 4 * BUF_BYTES + ((r + 8) * H0STR + col) * 2) = v1;
            acc[mi][ni][0] = 0.f; acc[mi][ni][1] = 0.f;
            acc[mi][ni][2] = 0.f; acc[mi][ni][3] = 0.f;
        }
    }

    // RACE FIX barrier
    __syncthreads();

    auto load2 = [&](int c, int buf) {
        int k0 = c * 32;
        #pragma unroll
        for (int i = 0; i < 2; i++) {
            int idx = tid + i * 256;
            int row = idx >> 2, seg = idx & 3;
            const __half* srcB = Wt1 + (long)row * 128 + k0 + seg * 8;
            cp_async16(sB + buf * BUF_BYTES + row * (SSTR * 2) + seg * 16, srcB, 16);
        }
        CP_COMMIT();
    };

    load2(0, 0);
    load2(1, 1);

    #pragma unroll
    for (int c = 0; c < 4; c++) {
        if (c < 3) CP_WAIT1(); else CP_WAIT0();
        __syncthreads();
        const int buf = c & 1;
        const int kcB = c * 64;
        const uint32_t bBase = sB + buf * BUF_BYTES;
        #pragma unroll
        for (int ks = 0; ks < 2; ks++) {
            const int kbB = ks * 32;
            uint32_t a[2][4], b[8][2];
            LDSM_X4(a[0][0], a[0][1], a[0][2], a[0][3], sH + aOffH + kcB + kbB);
            LDSM_X4(a[1][0], a[1][1], a[1][2], a[1][3], sH + aOffH + 16 * H0STR * 2 + kcB + kbB);
            #pragma unroll
            for (int j = 0; j < 4; j++)
                LDSM_X4(b[2 * j][0], b[2 * j][1], b[2 * j + 1][0], b[2 * j + 1][1],
                        bBase + bOff + j * 16 * SSTR * 2 + kbB);
            #pragma unroll
            for (int mi = 0; mi < 2; mi++)
                #pragma unroll
                for (int ni = 0; ni < 8; ni++)
                    MMA_F16(acc[mi][ni], a[mi], b[ni]);
        }
        if (c + 2 < 4) {
            __syncthreads();
            load2(c + 2, buf);
        }
    }

    #pragma unroll
    for (int mi = 0; mi < 2; mi++) {
        int row = m0 + wm * 32 + mi * 16 + gID;
        #pragma unroll
        for (int ni = 0; ni < 8; ni++) {
            int col = wn * 64 + ni * 8 + t4 * 2;
            if (row < M)
                *(__half2*)&C[(long)row * 128 + col] =
                    __floats2half2_rn(acc[mi][ni][0], acc[mi][ni][1]);
            if (row + 8 < M)
                *(__half2*)&C[(long)(row + 8) * 128 + col] =
                    __floats2half2_rn(acc[mi][ni][2], acc[mi][ni][3]);
        }
    }
}

// ---------------- fused agg + GEMM(s) ----------------
// h = relu(agg(xw)+abias) -> smem tile; CA = h @ WtA^T (+gbiasA); if WtB: CB = h @ WtB^T
__global__ void __launch_bounds__(256, 2) agg_gemm_kernel(
    const uint2* __restrict__ xw, const float* __restrict__ abias,
    const __half* __restrict__ WtA, const float* __restrict__ gbiasA,
    __half* __restrict__ CA,
    const __half* __restrict__ WtB, __half* __restrict__ CB,
    int M)
{
    pdl_trigger();
    extern __shared__ __half sm[];
    const uint32_t sB = smem_u32(sm);
    const uint32_t sH = sB + 2 * BUF_BYTES;

    const int tid = threadIdx.x;
    const int lane = tid & 31, wid = tid >> 5;
    const int gID = lane >> 2, t4 = lane & 3;
    const int wm = wid & 3, wn = wid >> 2;
    const int m0 = blockIdx.x * 128;

    const int lane15 = lane & 15;
    const uint32_t aOffH = (uint32_t)((wm * 32 + lane15) * H0STR) * 2 + (lane >> 4) * 16;
    const uint32_t bOff  = (uint32_t)((wn * 64 + ((lane >> 4) * 8) + (lane & 7)) * SSTR) * 2
                         + ((lane >> 3) & 1) * 16;

    pdl_wait();

    // phase 1: aggregation — warp handles 16 rows of the tile
    float4 ab = ((const float4*)abias)[lane];
    for (int i = 0; i < 16; i++) {
        int r = wid * 16 + i;
        int node = m0 + r;
        float4 acc4;
        if (node < M) {
            float di = g_dinv[node];
            float sl = di * di;
            uint2 sv = xw[node * 32 + lane];
            float2 s0 = __half22float2(*(__half2*)&sv.x);
            float2 s1 = __half22float2(*(__half2*)&sv.y);
            acc4 = make_float4(s0.x * sl, s0.y * sl, s1.x * sl, s1.y * sl);
            int p    = g_rowptr[node];
            int pend = g_rowptr[node + 1];
            for (int base = p; base < pend; base += 32) {
                int cnt = pend - base;
                if (cnt > 32) cnt = 32;
                int2 rec = make_int2(0, 0);
                if (base + lane < pend) rec = g_csr_sn[base + lane];
                for (int j = 0; j < cnt; j++) {
                    int s    = __shfl_sync(0xffffffff, rec.x, j);
                    float nm = __int_as_float(__shfl_sync(0xffffffff, rec.y, j));
                    uint2 uv = xw[s * 32 + lane];
                    float2 u0 = __half22float2(*(__half2*)&uv.x);
                    float2 u1 = __half22float2(*(__half2*)&uv.y);
                    acc4.x += u0.x * nm; acc4.y += u0.y * nm;
                    acc4.z += u1.x * nm; acc4.w += u1.y * nm;
                }
            }
            acc4.x = fmaxf(acc4.x + ab.x, 0.f);
            acc4.y = fmaxf(acc4.y + ab.y, 0.f);
            acc4.z = fmaxf(acc4.z + ab.z, 0.f);
            acc4.w = fmaxf(acc4.w + ab.w, 0.f);
        } else {
            acc4 = make_float4(0.f, 0.f, 0.f, 0.f);
        }
        uint2 o;
        *(__half2*)&o.x = __floats2half2_rn(acc4.x, acc4.y);
        *(__half2*)&o.y = __floats2half2_rn(acc4.z, acc4.w);
        *(uint2*)((char*)sm + 2 * BUF_BYTES + (r * H0STR + lane * 4) * 2) = o;
    }
    __syncthreads();   // h tile complete

    // phase 2: GEMM pass(es)
    float acc[2][8][4];
    #pragma unroll 1
    for (int pass = 0; pass < 2; pass++) {
        const __half* Wt = (pass == 0) ? WtA : WtB;
        const float*  gb = (pass == 0) ? gbiasA : nullptr;
        __half*       C  = (pass == 0) ? CA : CB;
        if (!Wt) break;

        #pragma unroll
        for (int mi = 0; mi < 2; mi++)
            #pragma unroll
            for (int ni = 0; ni < 8; ni++)
                #pragma unroll
                for (int j = 0; j < 4; j++) acc[mi][ni][j] = 0.f;

        auto loadB = [&](int c, int buf) {
            int k0 = c * 32;
            #pragma unroll
            for (int i = 0; i < 2; i++) {
                int idx = tid + i * 256;
                int row = idx >> 2, seg = idx & 3;
                const __half* srcB = Wt + (long)row * 128 + k0 + seg * 8;
                cp_async16(sB + buf * BUF_BYTES + row * (SSTR * 2) + seg * 16, srcB, 16);
            }
            CP_COMMIT();
        };

        loadB(0, 0);
        loadB(1, 1);

        #pragma unroll
        for (int c = 0; c < 4; c++) {
            if (c < 3) CP_WAIT1(); else CP_WAIT0();
            __syncthreads();
            const int buf = c & 1;
            const int kcB = c * 64;
            const uint32_t bBase = sB + buf * BUF_BYTES;
            #pragma unroll
            for (int ks = 0; ks < 2; ks++) {
                const int kbB = ks * 32;
                uint32_t a[2][4], b[8][2];
                LDSM_X4(a[0][0], a[0][1], a[0][2], a[0][3], sH + aOffH + kcB + kbB);
                LDSM_X4(a[1][0], a[1][1], a[1][2], a[1][3], sH + aOffH + 16 * H0STR * 2 + kcB + kbB);
                #pragma unroll
                for (int j = 0; j < 4; j++)
                    LDSM_X4(b[2 * j][0], b[2 * j][1], b[2 * j + 1][0], b[2 * j + 1][1],
                            bBase + bOff + j * 16 * SSTR * 2 + kbB);
                #pragma unroll
                for (int mi = 0; mi < 2; mi++)
                    #pragma unroll
                    for (int ni = 0; ni < 8; ni++)
                        MMA_F16(acc[mi][ni], a[mi], b[ni]);
            }
            if (c + 2 < 4) {
                __syncthreads();
                loadB(c + 2, buf);
            }
        }

        #pragma unroll
        for (int mi = 0; mi < 2; mi++) {
            int row = m0 + wm * 32 + mi * 16 + gID;
            #pragma unroll
            for (int ni = 0; ni < 8; ni++) {
                int col = wn * 64 + ni * 8 + t4 * 2;
                float bx = 0.f, by = 0.f;
                if (gb) { bx = gb[col]; by = gb[col + 1]; }
                if (row < M)
                    *(__half2*)&C[(long)row * 128 + col] =
                        __floats2half2_rn(acc[mi][ni][0] + bx, acc[mi][ni][1] + by);
                if (row + 8 < M)
                    *(__half2*)&C[(long)(row + 8) * 128 + col] =
                        __floats2half2_rn(acc[mi][ni][2] + bx, acc[mi][ni][3] + by);
            }
        }

        // drain all reads of sB before next pass overwrites it
        __syncthreads();
    }
}

// ---------------- edge MLP: batched CSR records, warp per dst-node ----------------
__global__ void edge_kernel(const uint2* __restrict__ Av, const uint2* __restrict__ Bv,
                            const float* __restrict__ Wm2, const float* __restrict__ bm2,
                            float* __restrict__ out) {
    pdl_trigger();
    int node = (blockIdx.x * blockDim.x + threadIdx.x) >> 5;
    int lane = threadIdx.x & 31;
    if (node >= N_NODES) return;
    pdl_wait();
    int p    = g_rowptr[node];
    int pend = g_rowptr[node + 1];
    if (p == pend) return;
    uint2 bv = Bv[node * 32 + lane];
    float2 b0 = __half22float2(*(__half2*)&bv.x);
    float2 b1 = __half22float2(*(__half2*)&bv.y);
    float4 w = ((const float4*)Wm2)[lane];
    float bm = bm2[0];
    for (int base = p; base < pend; base += 32) {
        int cnt = pend - base;
        if (cnt > 32) cnt = 32;
        int2 rec = make_int2(0, 0);
        if (base + lane < pend) rec = g_csr_se[base + lane];
        for (int j = 0; j < cnt; j++) {
            int s   = __shfl_sync(0xffffffff, rec.x, j);
            int eid = __shfl_sync(0xffffffff, rec.y, j);
            uint2 av = Av[s * 32 + lane];
            float2 a0 = __half22float2(*(__half2*)&av.x);
            float2 a1 = __half22float2(*(__half2*)&av.y);
            float sum = fmaxf(a0.x + b0.x, 0.f) * w.x
                      + fmaxf(a0.y + b0.y, 0.f) * w.y
                      + fmaxf(a1.x + b1.x, 0.f) * w.z
                      + fmaxf(a1.y + b1.y, 0.f) * w.w;
            #pragma unroll
            for (int off = 16; off > 0; off >>= 1)
                sum += __shfl_down_sync(0xffffffff, sum, off);
            if (lane == 0) out[eid] = sum + bm;
        }
    }
}

// ---------------- launch ----------------
static void launch_pdl(const void* fn, dim3 grid, dim3 block, size_t smem,
                       cudaStream_t st, void** args) {
    cudaLaunchConfig_t cfg = {};
    cfg.gridDim = grid; cfg.blockDim = block;
    cfg.dynamicSmemBytes = smem; cfg.stream = st;
    cudaLaunchAttribute attr[1];
    attr[0].id = cudaLaunchAttributeProgrammaticStreamSerialization;
    attr[0].val.programmaticStreamSerializationAllowed = 1;
    cfg.attrs = attr; cfg.numAttrs = 1;
    cudaLaunchKernelExC(&cfg, fn, args);
}

extern "C" void kernel_launch(void* const* d_in, const int* in_sizes, int n_in,
                              void* d_out, int out_size) {
    const float* x      = (const float*)d_in[0];
    const int*   eidx   = (const int*)d_in[1];
    const float* W_in   = (const float*)d_in[2];
    const float* b_in   = (const float*)d_in[3];
    const float* W1     = (const float*)d_in[4];
    const float* b1     = (const float*)d_in[5];
    const float* W2     = (const float*)d_in[6];
    const float* b2     = (const float*)d_in[7];
    const float* Wm1    = (const float*)d_in[8];
    const float* bm1    = (const float*)d_in[9];
    const float* Wm2    = (const float*)d_in[10];
    const float* bm2    = (const float*)d_in[11];
    float* out = (float*)d_out;

    const int* src = eidx;
    const int* dst = eidx + N_EDGES;

    float *buf0f, *buf1f, *buf2f, *buf3f;
    __half *wtin, *wt1, *wt2, *wtm1a, *wtm1b;
    cudaGetSymbolAddress((void**)&buf0f, g_buf0);
    cudaGetSymbolAddress((void**)&buf1f, g_buf1);
    cudaGetSymbolAddress((void**)&buf2f, g_buf2);
    cudaGetSymbolAddress((void**)&buf3f, g_buf3);
    cudaGetSymbolAddress((void**)&wtin, g_wt_in);
    cudaGetSymbolAddress((void**)&wt1, g_wt1);
    cudaGetSymbolAddress((void**)&wt2, g_wt2);
    cudaGetSymbolAddress((void**)&wtm1a, g_wtm1a);
    cudaGetSymbolAddress((void**)&wtm1b, g_wtm1b);

    __half* xh   = (__half*)buf3f;
    __half* xw1h = (__half*)buf0f;
    __half* xw2h = (__half*)buf1f;
    __half* Ah   = (__half*)buf2f;
    __half* Bh   = (__half*)buf2f + HALF_OFF;

    static cudaStream_t s2 = nullptr;
    static cudaEvent_t evF = nullptr, evJ = nullptr;
    if (!s2) {
        cudaStreamCreateWithFlags(&s2, cudaStreamNonBlocking);
        cudaEventCreateWithFlags(&evF, cudaEventDisableTiming);
        cudaEventCreateWithFlags(&evJ, cudaEventDisableTiming);
    }

    const int SMEMF  = 4 * BUF_BYTES + H0_BYTES;
    const int SMEMAG = 2 * BUF_BYTES + H0_BYTES;
    cudaFuncSetAttribute(gemm_fused_kernel, cudaFuncAttributeMaxDynamicSharedMemorySize, SMEMF);
    cudaFuncSetAttribute(agg_gemm_kernel,   cudaFuncAttributeMaxDynamicSharedMemorySize, SMEMAG);

    const int TPB = 256;
    dim3 nodeGrid((N_NODES + TPB - 1) / TPB);
    dim3 edgeGrid((N_EDGES + TPB - 1) / TPB);
    dim3 gemmGrid((N_NODES + 127) / 128, 1);
    dim3 warpNodeGrid((N_NODES * 32 + TPB - 1) / TPB);
    dim3 tpb(TPB, 1, 1);

    // ---- fork: CSR build on s2 ----
    cudaEventRecord(evF, 0);
    cudaStreamWaitEvent(s2, evF, 0);

    zero_deg_kernel<<<nodeGrid, TPB, 0, s2>>>();
    hist_kernel<<<edgeGrid, TPB, 0, s2>>>(dst);
    scan1_kernel<<<SCAN_BLOCKS, SCAN_TPB, 0, s2>>>();
    scan2_kernel<<<1, 32, 0, s2>>>();
    scan3_kernel<<<SCAN_BLOCKS, SCAN_TPB, 0, s2>>>();
    fill_kernel<<<edgeGrid, TPB, 0, s2>>>(src, dst);
    cudaEventRecord(evJ, s2);

    // main stream
    prep_kernel<<<CVT_BLOCKS + 48 + 4 * 64, TPB>>>(x, (__half2*)xh, W_in, W1, W2, Wm1,
                                                   wtin, wt1, wt2, wtm1a, wtm1b);

    // xw1 = relu(x@W_in+b_in) @ W1 — PDL after prep
    {
        static int M = N_NODES;
        void* a[] = {(void*)&xh, (void*)&wtin, (void*)&b_in, (void*)&wt1,
                     (void*)&xw1h, (void*)&M};
        launch_pdl((const void*)gemm_fused_kernel, gemmGrid, tpb, SMEMF, 0, a);
    }

    // ---- join: CSR ready before first aggregation ----
    cudaStreamWaitEvent(0, evJ, 0);

    // F1: h1 = relu(agg(xw1)+b1); xw2 = h1 @ W2  (normal launch — event dep)
    agg_gemm_kernel<<<gemmGrid, TPB, SMEMAG>>>((const uint2*)xw1h, b1, wt2, nullptr,
                                               xw2h, nullptr, nullptr, N_NODES);

    // F2: h2 = relu(agg(xw2)+b2); A = h2@Wm1a + bm1; B = h2@Wm1b — PDL after F1
    {
        static const uint2* xwp; static int M = N_NODES;
        xwp = (const uint2*)xw2h;
        void* a[] = {(void*)&xwp, (void*)&b2, (void*)&wtm1a, (void*)&bm1,
                     (void*)&Ah, (void*)&wtm1b, (void*)&Bh, (void*)&M};
        launch_pdl((const void*)agg_gemm_kernel, gemmGrid, tpb, SMEMAG, 0, a);
    }

    // edge logits — PDL after F2
    {
        static const uint2* av; static const uint2* bv2;
        av = (const uint2*)Ah; bv2 = (const uint2*)Bh;
        void* a[] = {(void*)&av, (void*)&bv2, (void*)&Wm2, (void*)&bm2, (void*)&out};
        launch_pdl((const void*)edge_kernel, warpNodeGrid, tpb, 0, 0, a);
    }
}

// round 15
// speedup vs baseline: 1.3766x; 1.3766x over previous
#include <cuda_runtime.h>
#include <cuda_fp16.h>
#include <cstdint>

#define N_NODES 50000
#define N_EDGES 800000
#define D_IN 96
#define HID 128
#define SCAN_TPB 1024
#define SCAN_BLOCKS ((N_NODES + SCAN_TPB - 1) / SCAN_TPB)   // 49
#define HALF_OFF (N_NODES * HID)

// ---------------- PDL helpers (sm_90+; legal under compute_103) ----------------
__device__ __forceinline__ void pdl_trigger() {
#if __CUDA_ARCH__ >= 900
    asm volatile("griddepcontrol.launch_dependents;");
#endif
}
__device__ __forceinline__ void pdl_wait() {
#if __CUDA_ARCH__ >= 900
    asm volatile("griddepcontrol.wait;" ::: "memory");
#endif
}

// ---------------- scratch (device globals; no allocation allowed) ----------------
__device__ __align__(16) float g_buf0[N_NODES * HID];
__device__ __align__(16) float g_buf1[N_NODES * HID];
__device__ __align__(16) float g_buf2[N_NODES * HID];
__device__ __align__(16) float g_buf3[N_NODES * HID];
__device__ __align__(16) __half g_wt_in[HID * D_IN];
__device__ __align__(16) __half g_wt1[HID * HID];
__device__ __align__(16) __half g_wt2[HID * HID];
__device__ __align__(16) __half g_wtm1a[HID * HID];
__device__ __align__(16) __half g_wtm1b[HID * HID];
__device__ float g_dinv[N_NODES];
__device__ int   g_deg[N_NODES];
__device__ int   g_rowptr[N_NODES + 1];
__device__ int   g_cursor[N_NODES];
__device__ int   g_partials[SCAN_BLOCKS + 1];
__device__ __align__(8) int2 g_csr_sn[N_EDGES];
__device__ __align__(8) int2 g_csr_se[N_EDGES];

// ---------------- graph preprocessing ----------------
__global__ void zero_deg_kernel() {
    int i = blockIdx.x * blockDim.x + threadIdx.x;
    if (i < N_NODES) g_deg[i] = 0;
}

__global__ void hist_kernel(const int* __restrict__ dst) {
    int e = blockIdx.x * blockDim.x + threadIdx.x;
    if (e < N_EDGES) atomicAdd(&g_deg[dst[e]], 1);
}

__global__ void scan1_kernel() {
    __shared__ int ws[32];
    int gid = blockIdx.x * SCAN_TPB + threadIdx.x;
    int lane = threadIdx.x & 31, wid = threadIdx.x >> 5;
    int v = (gid < N_NODES) ? g_deg[gid] : 0;
    if (gid < N_NODES) g_dinv[gid] = rsqrtf((float)(v + 1));
    int x = v;
    #pragma unroll
    for (int off = 1; off < 32; off <<= 1) {
        int t = __shfl_up_sync(0xffffffff, x, off);
        if (lane >= off) x += t;
    }
    if (lane == 31) ws[wid] = x;
    __syncthreads();
    if (wid == 0) {
        int t = ws[lane];
        #pragma unroll
        for (int off = 1; off < 32; off <<= 1) {
            int u = __shfl_up_sync(0xffffffff, t, off);
            if (lane >= off) t += u;
        }
        ws[lane] = t;
    }
    __syncthreads();
    int excl = (wid ? ws[wid - 1] : 0) + x - v;
    if (gid < N_NODES) g_rowptr[gid] = excl;
    if (threadIdx.x == 0) g_partials[blockIdx.x] = ws[31];
}

__global__ void scan2_kernel() {
    int lane = threadIdx.x;
    int v0 = (lane < SCAN_BLOCKS) ? g_partials[lane] : 0;
    int v1 = (lane + 32 < SCAN_BLOCKS) ? g_partials[lane + 32] : 0;
    int x0 = v0;
    #pragma unroll
    for (int off = 1; off < 32; off <<= 1) {
        int t = __shfl_up_sync(0xffffffff, x0, off);
        if (lane >= off) x0 += t;
    }
    int tot0 = __shfl_sync(0xffffffff, x0, 31);
    int x1 = v1;
    #pragma unroll
    for (int off = 1; off < 32; off <<= 1) {
        int t = __shfl_up_sync(0xffffffff, x1, off);
        if (lane >= off) x1 += t;
    }
    if (lane < SCAN_BLOCKS) g_partials[lane] = x0 - v0;
    if (lane + 32 < SCAN_BLOCKS) g_partials[lane + 32] = tot0 + x1 - v1;
    if (lane == 31) g_rowptr[N_NODES] = tot0 + __shfl_sync(0xffffffff, x1, 31);
}

__global__ void scan3_kernel() {
    int gid = blockIdx.x * SCAN_TPB + threadIdx.x;
    if (gid < N_NODES) {
        int r = g_rowptr[gid] + g_partials[blockIdx.x];
        g_rowptr[gid] = r;
        g_cursor[gid] = r;
    }
}

__global__ void fill_kernel(const int* __restrict__ src, const int* __restrict__ dst) {
    int e = blockIdx.x * blockDim.x + threadIdx.x;
    if (e < N_EDGES) {
        int s = src[e], d = dst[e];
        int p = atomicAdd(&g_cursor[d], 1);
        float nm = g_dinv[s] * g_dinv[d];
        g_csr_sn[p] = make_int2(s, __float_as_int(nm));
        g_csr_se[p] = make_int2(s, e);
    }
}

// ---------------- single prep kernel: cvt x -> fp16 AND all 5 weight transposes ----------------
#define CVT_ELEMS (N_NODES * D_IN / 4)
#define CVT_BLOCKS ((CVT_ELEMS + 255) / 256)
__global__ void prep_kernel(const float* __restrict__ x, __half2* __restrict__ xh,
                            const float* __restrict__ W_in, const float* __restrict__ W1,
                            const float* __restrict__ W2, const float* __restrict__ Wm1,
                            __half* __restrict__ wtin, __half* __restrict__ wt1,
                            __half* __restrict__ wt2, __half* __restrict__ wtm1a,
                            __half* __restrict__ wtm1b) {
    __shared__ float t[16][17];
    int b = blockIdx.x, tid = threadIdx.x;
    if (b < CVT_BLOCKS) {
        int i = b * 256 + tid;
        if (i < CVT_ELEMS) {
            float4 v = ((const float4*)x)[i];
            xh[i * 2]     = __floats2half2_rn(v.x, v.y);
            xh[i * 2 + 1] = __floats2half2_rn(v.z, v.w);
        }
        return;
    }
    int tb = b - CVT_BLOCKS;
    const float* W; __half* Wt; int K;
    if (tb < 48)       { W = W_in;            Wt = wtin;  K = 96;  }
    else if (tb < 112) { W = W1;              Wt = wt1;   K = 128; tb -= 48; }
    else if (tb < 176) { W = W2;              Wt = wt2;   K = 128; tb -= 112; }
    else if (tb < 240) { W = Wm1;             Wt = wtm1a; K = 128; tb -= 176; }
    else               { W = Wm1 + HID * HID; Wt = wtm1b; K = 128; tb -= 240; }
    int bx = tb % 8, by = tb / 8;
    int tx = tid & 15, ty = tid >> 4;
    int n = bx * 16 + tx, k = by * 16 + ty;
    if (k < K) t[ty][tx] = W[k * 128 + n];
    __syncthreads();
    int n2 = bx * 16 + ty, k2 = by * 16 + tx;
    if (k2 < K) Wt[n2 * K + k2] = __float2half(t[tx][ty]);
}

// ---------------- fp16 mma.sync GEMM machinery ----------------
#define SSTR 56
#define BUF_HALVES (128 * SSTR)
#define BUF_BYTES  (BUF_HALVES * 2)
#define H0STR 136
#define H0_BYTES (128 * H0STR * 2)

__device__ __forceinline__ uint32_t smem_u32(const void* p) {
    uint32_t a;
    asm("{ .reg .u64 t; cvta.to.shared.u64 t, %1; cvt.u32.u64 %0, t; }" : "=r"(a) : "l"(p));
    return a;
}
__device__ __forceinline__ void cp_async16(uint32_t dst, const void* src, int sz) {
    asm volatile("cp.async.ca.shared.global [%0], [%1], 16, %2;"
                 :: "r"(dst), "l"(src), "r"(sz) : "memory");
}
#define CP_COMMIT() asm volatile("cp.async.commit_group;" ::: "memory")
#define CP_WAIT1()  asm volatile("cp.async.wait_group 1;" ::: "memory")
#define CP_WAIT0()  asm volatile("cp.async.wait_group 0;" ::: "memory")

#define LDSM_X4(r0, r1, r2, r3, addr)                                          \
    asm volatile("ldmatrix.sync.aligned.m8n8.x4.shared.b16 {%0,%1,%2,%3}, [%4];" \
        : "=r"(r0), "=r"(r1), "=r"(r2), "=r"(r3) : "r"(addr))

#define MMA_F16(c, a, b)                                                       \
    asm volatile(                                                              \
        "mma.sync.aligned.m16n8k16.row.col.f32.f16.f16.f32 "                   \
        "{%0,%1,%2,%3}, {%4,%5,%6,%7}, {%8,%9}, {%0,%1,%2,%3};"                \
        : "+f"((c)[0]), "+f"((c)[1]), "+f"((c)[2]), "+f"((c)[3])               \
        : "r"((a)[0]), "r"((a)[1]), "r"((a)[2]), "r"((a)[3]),                  \
          "r"((b)[0]), "r"((b)[1]))

// ---------------- plain GEMM: C[M,128] = act(A[M,128] @ Wt[128,128]^T (+bias)) ----------------
__global__ void __launch_bounds__(256, 2) gemm_f16_kernel(
    const __half* __restrict__ A,
    const __half* __restrict__ W0, const float* __restrict__ bias0, __half* __restrict__ C0,
    const __half* __restrict__ W1, const float* __restrict__ bias1, __half* __restrict__ C1,
    int M, int do_relu)
{
    pdl_trigger();
    const __half* W    = (blockIdx.y == 0) ? W0 : W1;
    const float*  bias = (blockIdx.y == 0) ? bias0 : bias1;
    __half*       C    = (blockIdx.y == 0) ? C0 : C1;
    constexpr int K = 128;
    constexpr int NC = 4;

    extern __shared__ __half sm[];
    const uint32_t sA = smem_u32(sm);
    const uint32_t sB = sA + 2 * BUF_BYTES;

    const int tid = threadIdx.x;
    const int lane = tid & 31, wid = tid >> 5;
    const int gID = lane >> 2, t4 = lane & 3;
    const int wm = wid & 3, wn = wid >> 2;
    const int m0 = blockIdx.x * 128;

    const int lane15 = lane & 15;
    const uint32_t aOff  = (uint32_t)((wm * 32 + lane15) * SSTR) * 2 + (lane >> 4) * 16;
    const uint32_t bOff  = (uint32_t)((wn * 64 + ((lane >> 4) * 8) + (lane & 7)) * SSTR) * 2
                         + ((lane >> 3) & 1) * 16;

    float acc[2][8][4];
    #pragma unroll
    for (int mi = 0; mi < 2; mi++)
        #pragma unroll
        for (int ni = 0; ni < 8; ni++)
            #pragma unroll
            for (int j = 0; j < 4; j++) acc[mi][ni][j] = 0.f;

    auto load_chunk = [&](int c, int buf) {
        int k0 = c * 32;
        #pragma unroll
        for (int i = 0; i < 2; i++) {
            int idx = tid + i * 256;
            int row = idx >> 2, seg = idx & 3;
            int g = m0 + row;
            const __half* srcA = A + (long)((g < M) ? g : 0) * K + k0 + seg * 8;
            cp_async16(sA + buf * BUF_BYTES + row * (SSTR * 2) + seg * 16, srcA, (g < M) ? 16 : 0);
            const __half* srcB = W + (long)row * K + k0 + seg * 8;
            cp_async16(sB + buf * BUF_BYTES + row * (SSTR * 2) + seg * 16, srcB, 16);
        }
        CP_COMMIT();
    };

    pdl_wait();
    load_chunk(0, 0);
    load_chunk(1, 1);

    #pragma unroll
    for (int c = 0; c < NC; c++) {
        if (c < NC - 1) CP_WAIT1(); else CP_WAIT0();
        __syncthreads();
        const int buf = c & 1;
        const uint32_t aBase = sA + buf * BUF_BYTES;
        const uint32_t bBase = sB + buf * BUF_BYTES;
        #pragma unroll
        for (int ks = 0; ks < 2; ks++) {
            const int kbB = ks * 32;
            uint32_t a[2][4], b[8][2];
            LDSM_X4(a[0][0], a[0][1], a[0][2], a[0][3], aBase + aOff + kbB);
            LDSM_X4(a[1][0], a[1][1], a[1][2], a[1][3], aBase + aOff + 16 * SSTR * 2 + kbB);
            #pragma unroll
            for (int j = 0; j < 4; j++)
                LDSM_X4(b[2 * j][0], b[2 * j][1], b[2 * j + 1][0], b[2 * j + 1][1],
                        bBase + bOff + j * 16 * SSTR * 2 + kbB);
            #pragma unroll
            for (int mi = 0; mi < 2; mi++)
                #pragma unroll
                for (int ni = 0; ni < 8; ni++)
                    MMA_F16(acc[mi][ni], a[mi], b[ni]);
        }
        if (c + 2 < NC) {
            __syncthreads();
            load_chunk(c + 2, buf);
        }
    }

    #pragma unroll
    for (int mi = 0; mi < 2; mi++) {
        int row = m0 + wm * 32 + mi * 16 + gID;
        #pragma unroll
        for (int ni = 0; ni < 8; ni++) {
            int col = wn * 64 + ni * 8 + t4 * 2;
            float bx = 0.f, by = 0.f;
            if (bias) { bx = bias[col]; by = bias[col + 1]; }
            float2 v0 = make_float2(acc[mi][ni][0] + bx, acc[mi][ni][1] + by);
            float2 v1 = make_float2(acc[mi][ni][2] + bx, acc[mi][ni][3] + by);
            if (do_relu) {
                v0.x = fmaxf(v0.x, 0.f); v0.y = fmaxf(v0.y, 0.f);
                v1.x = fmaxf(v1.x, 0.f); v1.y = fmaxf(v1.y, 0.f);
            }
            if (row < M)
                *(__half2*)&C[(long)row * 128 + col] = __floats2half2_rn(v0.x, v0.y);
            if (row + 8 < M)
                *(__half2*)&C[(long)(row + 8) * 128 + col] = __floats2half2_rn(v1.x, v1.y);
        }
    }
}

// ---------------- fused GEMM: xw1 = (relu(x@W_in+b_in)) @ W1, h0 kept in smem ----------------
__global__ void __launch_bounds__(256, 2) gemm_fused_kernel(
    const __half* __restrict__ Xh,
    const __half* __restrict__ Wt0,
    const float* __restrict__ bias0,
    const __half* __restrict__ Wt1,
    __half* __restrict__ C,
    int M)
{
    pdl_trigger();
    extern __shared__ __half sm[];
    const uint32_t sA = smem_u32(sm);
    const uint32_t sB = sA + 2 * BUF_BYTES;
    const uint32_t sH = sB + 2 * BUF_BYTES;

    const int tid = threadIdx.x;
    const int lane = tid & 31, wid = tid >> 5;
    const int gID = lane >> 2, t4 = lane & 3;
    const int wm = wid & 3, wn = wid >> 2;
    const int m0 = blockIdx.x * 128;

    const int lane15 = lane & 15;
    const uint32_t aOff  = (uint32_t)((wm * 32 + lane15) * SSTR) * 2 + (lane >> 4) * 16;
    const uint32_t aOffH = (uint32_t)((wm * 32 + lane15) * H0STR) * 2 + (lane >> 4) * 16;
    const uint32_t bOff  = (uint32_t)((wn * 64 + ((lane >> 4) * 8) + (lane & 7)) * SSTR) * 2
                         + ((lane >> 3) & 1) * 16;

    float acc[2][8][4];
    #pragma unroll
    for (int mi = 0; mi < 2; mi++)
        #pragma unroll
        for (int ni = 0; ni < 8; ni++)
            #pragma unroll
            for (int j = 0; j < 4; j++) acc[mi][ni][j] = 0.f;

    auto load1 = [&](int c, int buf) {
        int k0 = c * 32;
        #pragma unroll
        for (int i = 0; i < 2; i++) {
            int idx = tid + i * 256;
            int row = idx >> 2, seg = idx & 3;
            int g = m0 + row;
            const __half* srcA = Xh + (long)((g < M) ? g : 0) * 96 + k0 + seg * 8;
            cp_async16(sA + buf * BUF_BYTES + row * (SSTR * 2) + seg * 16, srcA, (g < M) ? 16 : 0);
            const __half* srcB = Wt0 + (long)row * 96 + k0 + seg * 8;
            cp_async16(sB + buf * BUF_BYTES + row * (SSTR * 2) + seg * 16, srcB, 16);
        }
        CP_COMMIT();
    };

    pdl_wait();
    load1(0, 0);
    load1(1, 1);

    #pragma unroll
    for (int c = 0; c < 3; c++) {
        if (c < 2) CP_WAIT1(); else CP_WAIT0();
        __syncthreads();
        const int buf = c & 1;
        const uint32_t aBase = sA + buf * BUF_BYTES;
        const uint32_t bBase = sB + buf * BUF_BYTES;
        #pragma unroll
        for (int ks = 0; ks < 2; ks++) {
            const int kbB = ks * 32;
            uint32_t a[2][4], b[8][2];
            LDSM_X4(a[0][0], a[0][1], a[0][2], a[0][3], aBase + aOff + kbB);
            LDSM_X4(a[1][0], a[1][1], a[1][2], a[1][3], aBase + aOff + 16 * SSTR * 2 + kbB);
            #pragma unroll
            for (int j = 0; j < 4; j++)
                LDSM_X4(b[2 * j][0], b[2 * j][1], b[2 * j + 1][0], b[2 * j + 1][1],
                        bBase + bOff + j * 16 * SSTR * 2 + kbB);
            #pragma unroll
            for (int mi = 0; mi < 2; mi++)
                #pragma unroll
                for (int ni = 0; ni < 8; ni++)
                    MMA_F16(acc[mi][ni], a[mi], b[ni]);
        }
        if (c + 2 < 3) {
            __syncthreads();
            load1(c + 2, buf);
        }
    }

    // stage-1 epilogue: bias + relu, h0 tile -> smem
    #pragma unroll
    for (int mi = 0; mi < 2; mi++) {
        int r = wm * 32 + mi * 16 + gID;
        #pragma unroll
        for (int ni = 0; ni < 8; ni++) {
            int col = wn * 64 + ni * 8 + t4 * 2;
            float bx = bias0[col], by = bias0[col + 1];
            __half2 v0 = __floats2half2_rn(fmaxf(acc[mi][ni][0] + bx, 0.f),
                                           fmaxf(acc[mi][ni][1] + by, 0.f));
            __half2 v1 = __floats2half2_rn(fmaxf(acc[mi][ni][2] + bx, 0.f),
                                           fmaxf(acc[mi][ni][3] + by, 0.f));
            *(__half2*)((char*)sm + 4 * BUF_BYTES + (r * H0STR + col) * 2)       = v0;
            *(__half2*)((char*)sm + 4 * BUF_BYTES + ((r + 8) * H0STR + col) * 2) = v1;
            acc[mi][ni][0] = 0.f; acc[mi][ni][1] = 0.f;
            acc[mi][ni][2] = 0.f; acc[mi][ni][3] = 0.f;
        }
    }

    // RACE FIX barrier (stage-1 reads complete before stage-2 overwrites; publishes h0)
    __syncthreads();

    auto load2 = [&](int c, int buf) {
        int k0 = c * 32;
        #pragma unroll
        for (int i = 0; i < 2; i++) {
            int idx = tid + i * 256;
            int row = idx >> 2, seg = idx & 3;
            const __half* srcB = Wt1 + (long)row * 128 + k0 + seg * 8;
            cp_async16(sB + buf * BUF_BYTES + row * (SSTR * 2) + seg * 16, srcB, 16);
        }
        CP_COMMIT();
    };

    load2(0, 0);
    load2(1, 1);

    #pragma unroll
    for (int c = 0; c < 4; c++) {
        if (c < 3) CP_WAIT1(); else CP_WAIT0();
        __syncthreads();
        const int buf = c & 1;
        const int kcB = c * 64;
        const uint32_t bBase = sB + buf * BUF_BYTES;
        #pragma unroll
        for (int ks = 0; ks < 2; ks++) {
            const int kbB = ks * 32;
            uint32_t a[2][4], b[8][2];
            LDSM_X4(a[0][0], a[0][1], a[0][2], a[0][3], sH + aOffH + kcB + kbB);
            LDSM_X4(a[1][0], a[1][1], a[1][2], a[1][3], sH + aOffH + 16 * H0STR * 2 + kcB + kbB);
            #pragma unroll
            for (int j = 0; j < 4; j++)
                LDSM_X4(b[2 * j][0], b[2 * j][1], b[2 * j + 1][0], b[2 * j + 1][1],
                        bBase + bOff + j * 16 * SSTR * 2 + kbB);
            #pragma unroll
            for (int mi = 0; mi < 2; mi++)
                #pragma unroll
                for (int ni = 0; ni < 8; ni++)
                    MMA_F16(acc[mi][ni], a[mi], b[ni]);
        }
        if (c + 2 < 4) {
            __syncthreads();
            load2(c + 2, buf);
        }
    }

    #pragma unroll
    for (int mi = 0; mi < 2; mi++) {
        int row = m0 + wm * 32 + mi * 16 + gID;
        #pragma unroll
        for (int ni = 0; ni < 8; ni++) {
            int col = wn * 64 + ni * 8 + t4 * 2;
            if (row < M)
                *(__half2*)&C[(long)row * 128 + col] =
                    __floats2half2_rn(acc[mi][ni][0], acc[mi][ni][1]);
            if (row + 8 < M)
                *(__half2*)&C[(long)(row + 8) * 128 + col] =
                    __floats2half2_rn(acc[mi][ni][2], acc[mi][ni][3]);
        }
    }
}

// ---------------- GCN aggregation: batched CSR records + fp16 gather ----------------
__global__ void agg_kernel(const uint2* __restrict__ xw, const float* __restrict__ bias,
                           uint2* __restrict__ outh) {
    pdl_trigger();
    int node = (blockIdx.x * blockDim.x + threadIdx.x) >> 5;
    int lane = threadIdx.x & 31;
    if (node >= N_NODES) return;
    pdl_wait();
    float di = g_dinv[node];
    float sl = di * di;
    uint2 sv = xw[node * 32 + lane];
    float2 s0 = __half22float2(*(__half2*)&sv.x);
    float2 s1 = __half22float2(*(__half2*)&sv.y);
    float4 acc = make_float4(s0.x * sl, s0.y * sl, s1.x * sl, s1.y * sl);
    int p    = g_rowptr[node];
    int pend = g_rowptr[node + 1];
    for (int base = p; base < pend; base += 32) {
        int cnt = pend - base;
        if (cnt > 32) cnt = 32;
        int2 rec = make_int2(0, 0);
        if (base + lane < pend) rec = g_csr_sn[base + lane];
        for (int j = 0; j < cnt; j++) {
            int s    = __shfl_sync(0xffffffff, rec.x, j);
            float nm = __int_as_float(__shfl_sync(0xffffffff, rec.y, j));
            uint2 uv = xw[s * 32 + lane];
            float2 u0 = __half22float2(*(__half2*)&uv.x);
            float2 u1 = __half22float2(*(__half2*)&uv.y);
            acc.x += u0.x * nm; acc.y += u0.y * nm;
            acc.z += u1.x * nm; acc.w += u1.y * nm;
        }
    }
    float4 b = ((const float4*)bias)[lane];
    acc.x = fmaxf(acc.x + b.x, 0.f);
    acc.y = fmaxf(acc.y + b.y, 0.f);
    acc.z = fmaxf(acc.z + b.z, 0.f);
    acc.w = fmaxf(acc.w + b.w, 0.f);
    uint2 o;
    *(__half2*)&o.x = __floats2half2_rn(acc.x, acc.y);
    *(__half2*)&o.y = __floats2half2_rn(acc.z, acc.w);
    outh[node * 32 + lane] = o;
}

// ---------------- edge MLP: batched CSR records, warp per dst-node ----------------
__global__ void edge_kernel(const uint2* __restrict__ Av, const uint2* __restrict__ Bv,
                            const float* __restrict__ Wm2, const float* __restrict__ bm2,
                            float* __restrict__ out) {
    pdl_trigger();
    int node = (blockIdx.x * blockDim.x + threadIdx.x) >> 5;
    int lane = threadIdx.x & 31;
    if (node >= N_NODES) return;
    pdl_wait();
    int p    = g_rowptr[node];
    int pend = g_rowptr[node + 1];
    if (p == pend) return;
    uint2 bv = Bv[node * 32 + lane];
    float2 b0 = __half22float2(*(__half2*)&bv.x);
    float2 b1 = __half22float2(*(__half2*)&bv.y);
    float4 w = ((const float4*)Wm2)[lane];
    float bm = bm2[0];
    for (int base = p; base < pend; base += 32) {
        int cnt = pend - base;
        if (cnt > 32) cnt = 32;
        int2 rec = make_int2(0, 0);
        if (base + lane < pend) rec = g_csr_se[base + lane];
        for (int j = 0; j < cnt; j++) {
            int s   = __shfl_sync(0xffffffff, rec.x, j);
            int eid = __shfl_sync(0xffffffff, rec.y, j);
            uint2 av = Av[s * 32 + lane];
            float2 a0 = __half22float2(*(__half2*)&av.x);
            float2 a1 = __half22float2(*(__half2*)&av.y);
            float sum = fmaxf(a0.x + b0.x, 0.f) * w.x
                      + fmaxf(a0.y + b0.y, 0.f) * w.y
                      + fmaxf(a1.x + b1.x, 0.f) * w.z
                      + fmaxf(a1.y + b1.y, 0.f) * w.w;
            #pragma unroll
            for (int off = 16; off > 0; off >>= 1)
                sum += __shfl_down_sync(0xffffffff, sum, off);
            if (lane == 0) out[eid] = sum + bm;
        }
    }
}

// ---------------- launch ----------------
static void launch_pdl(const void* fn, dim3 grid, dim3 block, size_t smem,
                       cudaStream_t st, void** args) {
    cudaLaunchConfig_t cfg = {};
    cfg.gridDim = grid; cfg.blockDim = block;
    cfg.dynamicSmemBytes = smem; cfg.stream = st;
    cudaLaunchAttribute attr[1];
    attr[0].id = cudaLaunchAttributeProgrammaticStreamSerialization;
    attr[0].val.programmaticStreamSerializationAllowed = 1;
    cfg.attrs = attr; cfg.numAttrs = 1;
    cudaLaunchKernelExC(&cfg, fn, args);
}

extern "C" void kernel_launch(void* const* d_in, const int* in_sizes, int n_in,
                              void* d_out, int out_size) {
    const float* x      = (const float*)d_in[0];
    const int*   eidx   = (const int*)d_in[1];
    const float* W_in   = (const float*)d_in[2];
    const float* b_in   = (const float*)d_in[3];
    const float* W1     = (const float*)d_in[4];
    const float* b1     = (const float*)d_in[5];
    const float* W2     = (const float*)d_in[6];
    const float* b2     = (const float*)d_in[7];
    const float* Wm1    = (const float*)d_in[8];
    const float* bm1    = (const float*)d_in[9];
    const float* Wm2    = (const float*)d_in[10];
    const float* bm2    = (const float*)d_in[11];
    float* out = (float*)d_out;

    const int* src = eidx;
    const int* dst = eidx + N_EDGES;

    float *buf0f, *buf1f, *buf2f, *buf3f;
    __half *wtin, *wt1, *wt2, *wtm1a, *wtm1b;
    cudaGetSymbolAddress((void**)&buf0f, g_buf0);
    cudaGetSymbolAddress((void**)&buf1f, g_buf1);
    cudaGetSymbolAddress((void**)&buf2f, g_buf2);
    cudaGetSymbolAddress((void**)&buf3f, g_buf3);
    cudaGetSymbolAddress((void**)&wtin, g_wt_in);
    cudaGetSymbolAddress((void**)&wt1, g_wt1);
    cudaGetSymbolAddress((void**)&wt2, g_wt2);
    cudaGetSymbolAddress((void**)&wtm1a, g_wtm1a);
    cudaGetSymbolAddress((void**)&wtm1b, g_wtm1b);

    __half* xh   = (__half*)buf3f;
    __half* xw1h = (__half*)buf0f;
    __half* h1h  = (__half*)buf0f + HALF_OFF;
    __half* xw2h = (__half*)buf1f;
    __half* h2h  = (__half*)buf1f + HALF_OFF;
    __half* Ah   = (__half*)buf2f;
    __half* Bh   = (__half*)buf2f + HALF_OFF;

    static cudaStream_t s2 = nullptr;
    static cudaEvent_t evF = nullptr, evJ = nullptr;
    if (!s2) {
        cudaStreamCreateWithFlags(&s2, cudaStreamNonBlocking);
        cudaEventCreateWithFlags(&evF, cudaEventDisableTiming);
        cudaEventCreateWithFlags(&evJ, cudaEventDisableTiming);
    }

    const int SMEM  = 4 * BUF_BYTES;
    const int SMEMF = 4 * BUF_BYTES + H0_BYTES;
    cudaFuncSetAttribute(gemm_f16_kernel,   cudaFuncAttributeMaxDynamicSharedMemorySize, SMEM);
    cudaFuncSetAttribute(gemm_fused_kernel, cudaFuncAttributeMaxDynamicSharedMemorySize, SMEMF);

    const int TPB = 256;
    dim3 nodeGrid((N_NODES + TPB - 1) / TPB);
    dim3 edgeGrid((N_EDGES + TPB - 1) / TPB);
    dim3 gemmGrid((N_NODES + 127) / 128, 1);
    dim3 gemmGrid2((N_NODES + 127) / 128, 2);
    dim3 warpNodeGrid((N_NODES * 32 + TPB - 1) / TPB);
    dim3 tpb(TPB, 1, 1);

    // ---- fork: CSR build on s2, concurrent with prep + fused GEMM ----
    cudaEventRecord(evF, 0);
    cudaStreamWaitEvent(s2, evF, 0);

    zero_deg_kernel<<<nodeGrid, TPB, 0, s2>>>();
    hist_kernel<<<edgeGrid, TPB, 0, s2>>>(dst);
    scan1_kernel<<<SCAN_BLOCKS, SCAN_TPB, 0, s2>>>();
    scan2_kernel<<<1, 32, 0, s2>>>();
    scan3_kernel<<<SCAN_BLOCKS, SCAN_TPB, 0, s2>>>();
    fill_kernel<<<edgeGrid, TPB, 0, s2>>>(src, dst);
    cudaEventRecord(evJ, s2);

    // main stream: prep (x cvt + all weight transposes) in ONE launch
    prep_kernel<<<CVT_BLOCKS + 48 + 4 * 64, TPB>>>(x, (__half2*)xh, W_in, W1, W2, Wm1,
                                                   wtin, wt1, wt2, wtm1a, wtm1b);

    // xw1 = relu(x@W_in+b_in) @ W1 (fused) — PDL after prep
    {
        static int M = N_NODES;
        void* a[] = {(void*)&xh, (void*)&wtin, (void*)&b_in, (void*)&wt1,
                     (void*)&xw1h, (void*)&M};
        launch_pdl((const void*)gemm_fused_kernel, gemmGrid, tpb, SMEMF, 0, a);
    }

    // ---- join before first aggregation (no PDL across the event) ----
    cudaStreamWaitEvent(0, evJ, 0);

    // h1 = relu(agg(xw1) + b1) — normal launch (has event dependency)
    agg_kernel<<<warpNodeGrid, TPB>>>((const uint2*)xw1h, b1, (uint2*)h1h);

    // xw2 = h1 @ W2 — PDL after agg1
    {
        static const __half* nW1 = nullptr; static const float* nB1 = nullptr;
        static __half* nC1 = nullptr; static int M = N_NODES; static int relu0 = 0;
        void* a[] = {(void*)&h1h, (void*)&wt2, (void*)&nB1, (void*)&xw2h,
                     (void*)&nW1, (void*)&nB1, (void*)&nC1, (void*)&M, (void*)&relu0};
        launch_pdl((const void*)gemm_f16_kernel, gemmGrid, tpb, SMEM, 0, a);
    }

    // h2 = relu(agg(xw2) + b2) — PDL after gemm2
    {
        static const uint2* in2; static const float* bb; static uint2* oo;
        in2 = (const uint2*)xw2h; bb = b2; oo = (uint2*)h2h;
        void* a[] = {(void*)&in2, (void*)&bb, (void*)&oo};
        launch_pdl((const void*)agg_kernel, warpNodeGrid, tpb, 0, 0, a);
    }

    // A = h2 @ Wm1a + bm1 ; B = h2 @ Wm1b — PDL after agg2
    {
        static int M = N_NODES; static int relu0 = 0;
        static const float* nullBias = nullptr;
        void* a[] = {(void*)&h2h, (void*)&wtm1a, (void*)&bm1, (void*)&Ah,
                     (void*)&wtm1b, (void*)&nullBias, (void*)&Bh, (void*)&M, (void*)&relu0};
        launch_pdl((const void*)gemm_f16_kernel, gemmGrid2, tpb, SMEM, 0, a);
    }

    // logits per edge — PDL after gemmAB
    {
        static const uint2* av; static const uint2* bv2;
        av = (const uint2*)Ah; bv2 = (const uint2*)Bh;
        void* a[] = {(void*)&av, (void*)&bv2, (void*)&Wm2, (void*)&bm2, (void*)&out};
        launch_pdl((const void*)edge_kernel, warpNodeGrid, tpb, 0, 0, a);
    }
}

// round 16
// speedup vs baseline: 1.3831x; 1.0047x over previous
#include <cuda_runtime.h>
#include <cuda_fp16.h>
#include <cstdint>

#define N_NODES 50000
#define N_EDGES 800000
#define D_IN 96
#define HID 128
#define SCAN_TPB 1024
#define SCAN_BLOCKS ((N_NODES + SCAN_TPB - 1) / SCAN_TPB)   // 49
#define HALF_OFF (N_NODES * HID)

// ---------------- PDL helpers (sm_90+; legal under compute_103) ----------------
__device__ __forceinline__ void pdl_trigger() {
#if __CUDA_ARCH__ >= 900
    asm volatile("griddepcontrol.launch_dependents;");
#endif
}
__device__ __forceinline__ void pdl_wait() {
#if __CUDA_ARCH__ >= 900
    asm volatile("griddepcontrol.wait;" ::: "memory");
#endif
}

// ---------------- scratch (device globals; no allocation allowed) ----------------
__device__ __align__(16) float g_buf0[N_NODES * HID];
__device__ __align__(16) float g_buf1[N_NODES * HID];
__device__ __align__(16) float g_buf2[N_NODES * HID];
__device__ __align__(16) float g_buf3[N_NODES * HID];
__device__ __align__(16) __half g_wt_in[HID * D_IN];
__device__ __align__(16) __half g_wt1[HID * HID];
__device__ __align__(16) __half g_wt2[HID * HID];
__device__ __align__(16) __half g_wtm1a[HID * HID];
__device__ __align__(16) __half g_wtm1b[HID * HID];
__device__ float g_dinv[N_NODES];
__device__ int   g_deg[N_NODES];
__device__ int   g_rowptr[N_NODES + 1];
__device__ int   g_cursor[N_NODES];
__device__ int   g_partials[SCAN_BLOCKS + 1];
__device__ __align__(8) int2 g_csr_sn[N_EDGES];
__device__ __align__(8) int2 g_csr_se[N_EDGES];

// ---------------- graph preprocessing ----------------
__global__ void zero_deg_kernel() {
    int i = blockIdx.x * blockDim.x + threadIdx.x;
    if (i < N_NODES) g_deg[i] = 0;
}

__global__ void hist_kernel(const int* __restrict__ dst) {
    int e = blockIdx.x * blockDim.x + threadIdx.x;
    if (e < N_EDGES) atomicAdd(&g_deg[dst[e]], 1);
}

__global__ void scan1_kernel() {
    __shared__ int ws[32];
    int gid = blockIdx.x * SCAN_TPB + threadIdx.x;
    int lane = threadIdx.x & 31, wid = threadIdx.x >> 5;
    int v = (gid < N_NODES) ? g_deg[gid] : 0;
    if (gid < N_NODES) g_dinv[gid] = rsqrtf((float)(v + 1));
    int x = v;
    #pragma unroll
    for (int off = 1; off < 32; off <<= 1) {
        int t = __shfl_up_sync(0xffffffff, x, off);
        if (lane >= off) x += t;
    }
    if (lane == 31) ws[wid] = x;
    __syncthreads();
    if (wid == 0) {
        int t = ws[lane];
        #pragma unroll
        for (int off = 1; off < 32; off <<= 1) {
            int u = __shfl_up_sync(0xffffffff, t, off);
            if (lane >= off) t += u;
        }
        ws[lane] = t;
    }
    __syncthreads();
    int excl = (wid ? ws[wid - 1] : 0) + x - v;
    if (gid < N_NODES) g_rowptr[gid] = excl;
    if (threadIdx.x == 0) g_partials[blockIdx.x] = ws[31];
}

__global__ void scan2_kernel() {
    int lane = threadIdx.x;
    int v0 = (lane < SCAN_BLOCKS) ? g_partials[lane] : 0;
    int v1 = (lane + 32 < SCAN_BLOCKS) ? g_partials[lane + 32] : 0;
    int x0 = v0;
    #pragma unroll
    for (int off = 1; off < 32; off <<= 1) {
        int t = __shfl_up_sync(0xffffffff, x0, off);
        if (lane >= off) x0 += t;
    }
    int tot0 = __shfl_sync(0xffffffff, x0, 31);
    int x1 = v1;
    #pragma unroll
    for (int off = 1; off < 32; off <<= 1) {
        int t = __shfl_up_sync(0xffffffff, x1, off);
        if (lane >= off) x1 += t;
    }
    if (lane < SCAN_BLOCKS) g_partials[lane] = x0 - v0;
    if (lane + 32 < SCAN_BLOCKS) g_partials[lane + 32] = tot0 + x1 - v1;
    if (lane == 31) g_rowptr[N_NODES] = tot0 + __shfl_sync(0xffffffff, x1, 31);
}

__global__ void scan3_kernel() {
    int gid = blockIdx.x * SCAN_TPB + threadIdx.x;
    if (gid < N_NODES) {
        int r = g_rowptr[gid] + g_partials[blockIdx.x];
        g_rowptr[gid] = r;
        g_cursor[gid] = r;
    }
}

__global__ void fill_kernel(const int* __restrict__ src, const int* __restrict__ dst) {
    int e = blockIdx.x * blockDim.x + threadIdx.x;
    if (e < N_EDGES) {
        int s = src[e], d = dst[e];
        int p = atomicAdd(&g_cursor[d], 1);
        float nm = g_dinv[s] * g_dinv[d];
        g_csr_sn[p] = make_int2(s, __float_as_int(nm));
        g_csr_se[p] = make_int2(s, e);
    }
}

// ---------------- single prep kernel ----------------
#define CVT_ELEMS (N_NODES * D_IN / 4)
#define CVT_BLOCKS ((CVT_ELEMS + 255) / 256)
__global__ void prep_kernel(const float* __restrict__ x, __half2* __restrict__ xh,
                            const float* __restrict__ W_in, const float* __restrict__ W1,
                            const float* __restrict__ W2, const float* __restrict__ Wm1,
                            __half* __restrict__ wtin, __half* __restrict__ wt1,
                            __half* __restrict__ wt2, __half* __restrict__ wtm1a,
                            __half* __restrict__ wtm1b) {
    __shared__ float t[16][17];
    int b = blockIdx.x, tid = threadIdx.x;
    if (b < CVT_BLOCKS) {
        int i = b * 256 + tid;
        if (i < CVT_ELEMS) {
            float4 v = ((const float4*)x)[i];
            xh[i * 2]     = __floats2half2_rn(v.x, v.y);
            xh[i * 2 + 1] = __floats2half2_rn(v.z, v.w);
        }
        return;
    }
    int tb = b - CVT_BLOCKS;
    const float* W; __half* Wt; int K;
    if (tb < 48)       { W = W_in;            Wt = wtin;  K = 96;  }
    else if (tb < 112) { W = W1;              Wt = wt1;   K = 128; tb -= 48; }
    else if (tb < 176) { W = W2;              Wt = wt2;   K = 128; tb -= 112; }
    else if (tb < 240) { W = Wm1;             Wt = wtm1a; K = 128; tb -= 176; }
    else               { W = Wm1 + HID * HID; Wt = wtm1b; K = 128; tb -= 240; }
    int bx = tb % 8, by = tb / 8;
    int tx = tid & 15, ty = tid >> 4;
    int n = bx * 16 + tx, k = by * 16 + ty;
    if (k < K) t[ty][tx] = W[k * 128 + n];
    __syncthreads();
    int n2 = bx * 16 + ty, k2 = by * 16 + tx;
    if (k2 < K) Wt[n2 * K + k2] = __float2half(t[tx][ty]);
}

// ---------------- fp16 mma.sync GEMM machinery ----------------
#define SSTR 56
#define BUF_HALVES (128 * SSTR)
#define BUF_BYTES  (BUF_HALVES * 2)
#define H0STR 136
#define H0_BYTES (128 * H0STR * 2)

__device__ __forceinline__ uint32_t smem_u32(const void* p) {
    uint32_t a;
    asm("{ .reg .u64 t; cvta.to.shared.u64 t, %1; cvt.u32.u64 %0, t; }" : "=r"(a) : "l"(p));
    return a;
}
__device__ __forceinline__ void cp_async16(uint32_t dst, const void* src, int sz) {
    asm volatile("cp.async.ca.shared.global [%0], [%1], 16, %2;"
                 :: "r"(dst), "l"(src), "r"(sz) : "memory");
}
#define CP_COMMIT() asm volatile("cp.async.commit_group;" ::: "memory")
#define CP_WAIT1()  asm volatile("cp.async.wait_group 1;" ::: "memory")
#define CP_WAIT0()  asm volatile("cp.async.wait_group 0;" ::: "memory")

#define LDSM_X4(r0, r1, r2, r3, addr)                                          \
    asm volatile("ldmatrix.sync.aligned.m8n8.x4.shared.b16 {%0,%1,%2,%3}, [%4];" \
        : "=r"(r0), "=r"(r1), "=r"(r2), "=r"(r3) : "r"(addr))

#define MMA_F16(c, a, b)                                                       \
    asm volatile(                                                              \
        "mma.sync.aligned.m16n8k16.row.col.f32.f16.f16.f32 "                   \
        "{%0,%1,%2,%3}, {%4,%5,%6,%7}, {%8,%9}, {%0,%1,%2,%3};"                \
        : "+f"((c)[0]), "+f"((c)[1]), "+f"((c)[2]), "+f"((c)[3])               \
        : "r"((a)[0]), "r"((a)[1]), "r"((a)[2]), "r"((a)[3]),                  \
          "r"((b)[0]), "r"((b)[1]))

// ---------------- plain GEMM ----------------
__global__ void __launch_bounds__(256, 2) gemm_f16_kernel(
    const __half* __restrict__ A,
    const __half* __restrict__ W0, const float* __restrict__ bias0, __half* __restrict__ C0,
    const __half* __restrict__ W1, const float* __restrict__ bias1, __half* __restrict__ C1,
    int M, int do_relu)
{
    pdl_trigger();
    const __half* W    = (blockIdx.y == 0) ? W0 : W1;
    const float*  bias = (blockIdx.y == 0) ? bias0 : bias1;
    __half*       C    = (blockIdx.y == 0) ? C0 : C1;
    constexpr int K = 128;
    constexpr int NC = 4;

    extern __shared__ __half sm[];
    const uint32_t sA = smem_u32(sm);
    const uint32_t sB = sA + 2 * BUF_BYTES;

    const int tid = threadIdx.x;
    const int lane = tid & 31, wid = tid >> 5;
    const int gID = lane >> 2, t4 = lane & 3;
    const int wm = wid & 3, wn = wid >> 2;
    const int m0 = blockIdx.x * 128;

    const int lane15 = lane & 15;
    const uint32_t aOff  = (uint32_t)((wm * 32 + lane15) * SSTR) * 2 + (lane >> 4) * 16;
    const uint32_t bOff  = (uint32_t)((wn * 64 + ((lane >> 4) * 8) + (lane & 7)) * SSTR) * 2
                         + ((lane >> 3) & 1) * 16;

    float acc[2][8][4];
    #pragma unroll
    for (int mi = 0; mi < 2; mi++)
        #pragma unroll
        for (int ni = 0; ni < 8; ni++)
            #pragma unroll
            for (int j = 0; j < 4; j++) acc[mi][ni][j] = 0.f;

    auto load_chunk = [&](int c, int buf) {
        int k0 = c * 32;
        #pragma unroll
        for (int i = 0; i < 2; i++) {
            int idx = tid + i * 256;
            int row = idx >> 2, seg = idx & 3;
            int g = m0 + row;
            const __half* srcA = A + (long)((g < M) ? g : 0) * K + k0 + seg * 8;
            cp_async16(sA + buf * BUF_BYTES + row * (SSTR * 2) + seg * 16, srcA, (g < M) ? 16 : 0);
            const __half* srcB = W + (long)row * K + k0 + seg * 8;
            cp_async16(sB + buf * BUF_BYTES + row * (SSTR * 2) + seg * 16, srcB, 16);
        }
        CP_COMMIT();
    };

    pdl_wait();
    load_chunk(0, 0);
    load_chunk(1, 1);

    #pragma unroll
    for (int c = 0; c < NC; c++) {
        if (c < NC - 1) CP_WAIT1(); else CP_WAIT0();
        __syncthreads();
        const int buf = c & 1;
        const uint32_t aBase = sA + buf * BUF_BYTES;
        const uint32_t bBase = sB + buf * BUF_BYTES;
        #pragma unroll
        for (int ks = 0; ks < 2; ks++) {
            const int kbB = ks * 32;
            uint32_t a[2][4], b[8][2];
            LDSM_X4(a[0][0], a[0][1], a[0][2], a[0][3], aBase + aOff + kbB);
            LDSM_X4(a[1][0], a[1][1], a[1][2], a[1][3], aBase + aOff + 16 * SSTR * 2 + kbB);
            #pragma unroll
            for (int j = 0; j < 4; j++)
                LDSM_X4(b[2 * j][0], b[2 * j][1], b[2 * j + 1][0], b[2 * j + 1][1],
                        bBase + bOff + j * 16 * SSTR * 2 + kbB);
            #pragma unroll
            for (int mi = 0; mi < 2; mi++)
                #pragma unroll
                for (int ni = 0; ni < 8; ni++)
                    MMA_F16(acc[mi][ni], a[mi], b[ni]);
        }
        if (c + 2 < NC) {
            __syncthreads();
            load_chunk(c + 2, buf);
        }
    }

    #pragma unroll
    for (int mi = 0; mi < 2; mi++) {
        int row = m0 + wm * 32 + mi * 16 + gID;
        #pragma unroll
        for (int ni = 0; ni < 8; ni++) {
            int col = wn * 64 + ni * 8 + t4 * 2;
            float bx = 0.f, by = 0.f;
            if (bias) { bx = bias[col]; by = bias[col + 1]; }
            float2 v0 = make_float2(acc[mi][ni][0] + bx, acc[mi][ni][1] + by);
            float2 v1 = make_float2(acc[mi][ni][2] + bx, acc[mi][ni][3] + by);
            if (do_relu) {
                v0.x = fmaxf(v0.x, 0.f); v0.y = fmaxf(v0.y, 0.f);
                v1.x = fmaxf(v1.x, 0.f); v1.y = fmaxf(v1.y, 0.f);
            }
            if (row < M)
                *(__half2*)&C[(long)row * 128 + col] = __floats2half2_rn(v0.x, v0.y);
            if (row + 8 < M)
                *(__half2*)&C[(long)(row + 8) * 128 + col] = __floats2half2_rn(v1.x, v1.y);
        }
    }
}

// ---------------- fused GEMM: xw1 = (relu(x@W_in+b_in)) @ W1, h0 kept in smem ----------------
__global__ void __launch_bounds__(256, 2) gemm_fused_kernel(
    const __half* __restrict__ Xh,
    const __half* __restrict__ Wt0,
    const float* __restrict__ bias0,
    const __half* __restrict__ Wt1,
    __half* __restrict__ C,
    int M)
{
    pdl_trigger();
    extern __shared__ __half sm[];
    const uint32_t sA = smem_u32(sm);
    const uint32_t sB = sA + 2 * BUF_BYTES;
    const uint32_t sH = sB + 2 * BUF_BYTES;

    const int tid = threadIdx.x;
    const int lane = tid & 31, wid = tid >> 5;
    const int gID = lane >> 2, t4 = lane & 3;
    const int wm = wid & 3, wn = wid >> 2;
    const int m0 = blockIdx.x * 128;

    const int lane15 = lane & 15;
    const uint32_t aOff  = (uint32_t)((wm * 32 + lane15) * SSTR) * 2 + (lane >> 4) * 16;
    const uint32_t aOffH = (uint32_t)((wm * 32 + lane15) * H0STR) * 2 + (lane >> 4) * 16;
    const uint32_t bOff  = (uint32_t)((wn * 64 + ((lane >> 4) * 8) + (lane & 7)) * SSTR) * 2
                         + ((lane >> 3) & 1) * 16;

    float acc[2][8][4];
    #pragma unroll
    for (int mi = 0; mi < 2; mi++)
        #pragma unroll
        for (int ni = 0; ni < 8; ni++)
            #pragma unroll
            for (int j = 0; j < 4; j++) acc[mi][ni][j] = 0.f;

    auto load1 = [&](int c, int buf) {
        int k0 = c * 32;
        #pragma unroll
        for (int i = 0; i < 2; i++) {
            int idx = tid + i * 256;
            int row = idx >> 2, seg = idx & 3;
            int g = m0 + row;
            const __half* srcA = Xh + (long)((g < M) ? g : 0) * 96 + k0 + seg * 8;
            cp_async16(sA + buf * BUF_BYTES + row * (SSTR * 2) + seg * 16, srcA, (g < M) ? 16 : 0);
            const __half* srcB = Wt0 + (long)row * 96 + k0 + seg * 8;
            cp_async16(sB + buf * BUF_BYTES + row * (SSTR * 2) + seg * 16, srcB, 16);
        }
        CP_COMMIT();
    };

    pdl_wait();
    load1(0, 0);
    load1(1, 1);

    #pragma unroll
    for (int c = 0; c < 3; c++) {
        if (c < 2) CP_WAIT1(); else CP_WAIT0();
        __syncthreads();
        const int buf = c & 1;
        const uint32_t aBase = sA + buf * BUF_BYTES;
        const uint32_t bBase = sB + buf * BUF_BYTES;
        #pragma unroll
        for (int ks = 0; ks < 2; ks++) {
            const int kbB = ks * 32;
            uint32_t a[2][4], b[8][2];
            LDSM_X4(a[0][0], a[0][1], a[0][2], a[0][3], aBase + aOff + kbB);
            LDSM_X4(a[1][0], a[1][1], a[1][2], a[1][3], aBase + aOff + 16 * SSTR * 2 + kbB);
            #pragma unroll
            for (int j = 0; j < 4; j++)
                LDSM_X4(b[2 * j][0], b[2 * j][1], b[2 * j + 1][0], b[2 * j + 1][1],
                        bBase + bOff + j * 16 * SSTR * 2 + kbB);
            #pragma unroll
            for (int mi = 0; mi < 2; mi++)
                #pragma unroll
                for (int ni = 0; ni < 8; ni++)
                    MMA_F16(acc[mi][ni], a[mi], b[ni]);
        }
        if (c + 2 < 3) {
            __syncthreads();
            load1(c + 2, buf);
        }
    }

    // stage-1 epilogue: bias + relu, h0 tile -> smem
    #pragma unroll
    for (int mi = 0; mi < 2; mi++) {
        int r = wm * 32 + mi * 16 + gID;
        #pragma unroll
        for (int ni = 0; ni < 8; ni++) {
            int col = wn * 64 + ni * 8 + t4 * 2;
            float bx = bias0[col], by = bias0[col + 1];
            __half2 v0 = __floats2half2_rn(fmaxf(acc[mi][ni][0] + bx, 0.f),
                                           fmaxf(acc[mi][ni][1] + by, 0.f));
            __half2 v1 = __floats2half2_rn(fmaxf(acc[mi][ni][2] + bx, 0.f),
                                           fmaxf(acc[mi][ni][3] + by, 0.f));
            *(__half2*)((char*)sm + 4 * BUF_BYTES + (r * H0STR + col) * 2)       = v0;
            *(__half2*)((char*)sm + 4 * BUF_BYTES + ((r + 8) * H0STR + col) * 2) = v1;
            acc[mi][ni][0] = 0.f; acc[mi][ni][1] = 0.f;
            acc[mi][ni][2] = 0.f; acc[mi][ni][3] = 0.f;
        }
    }

    // RACE FIX barrier
    __syncthreads();

    auto load2 = [&](int c, int buf) {
        int k0 = c * 32;
        #pragma unroll
        for (int i = 0; i < 2; i++) {
            int idx = tid + i * 256;
            int row = idx >> 2, seg = idx & 3;
            const __half* srcB = Wt1 + (long)row * 128 + k0 + seg * 8;
            cp_async16(sB + buf * BUF_BYTES + row * (SSTR * 2) + seg * 16, srcB, 16);
        }
        CP_COMMIT();
    };

    load2(0, 0);
    load2(1, 1);

    #pragma unroll
    for (int c = 0; c < 4; c++) {
        if (c < 3) CP_WAIT1(); else CP_WAIT0();
        __syncthreads();
        const int buf = c & 1;
        const int kcB = c * 64;
        const uint32_t bBase = sB + buf * BUF_BYTES;
        #pragma unroll
        for (int ks = 0; ks < 2; ks++) {
            const int kbB = ks * 32;
            uint32_t a[2][4], b[8][2];
            LDSM_X4(a[0][0], a[0][1], a[0][2], a[0][3], sH + aOffH + kcB + kbB);
            LDSM_X4(a[1][0], a[1][1], a[1][2], a[1][3], sH + aOffH + 16 * H0STR * 2 + kcB + kbB);
            #pragma unroll
            for (int j = 0; j < 4; j++)
                LDSM_X4(b[2 * j][0], b[2 * j][1], b[2 * j + 1][0], b[2 * j + 1][1],
                        bBase + bOff + j * 16 * SSTR * 2 + kbB);
            #pragma unroll
            for (int mi = 0; mi < 2; mi++)
                #pragma unroll
                for (int ni = 0; ni < 8; ni++)
                    MMA_F16(acc[mi][ni], a[mi], b[ni]);
        }
        if (c + 2 < 4) {
            __syncthreads();
            load2(c + 2, buf);
        }
    }

    #pragma unroll
    for (int mi = 0; mi < 2; mi++) {
        int row = m0 + wm * 32 + mi * 16 + gID;
        #pragma unroll
        for (int ni = 0; ni < 8; ni++) {
            int col = wn * 64 + ni * 8 + t4 * 2;
            if (row < M)
                *(__half2*)&C[(long)row * 128 + col] =
                    __floats2half2_rn(acc[mi][ni][0], acc[mi][ni][1]);
            if (row + 8 < M)
                *(__half2*)&C[(long)(row + 8) * 128 + col] =
                    __floats2half2_rn(acc[mi][ni][2], acc[mi][ni][3]);
        }
    }
}

// ---------------- GCN aggregation: batched CSR records, 4-wide MLP ----------------
__global__ void agg_kernel(const uint2* __restrict__ xw, const float* __restrict__ bias,
                           uint2* __restrict__ outh) {
    pdl_trigger();
    int node = (blockIdx.x * blockDim.x + threadIdx.x) >> 5;
    int lane = threadIdx.x & 31;
    if (node >= N_NODES) return;
    pdl_wait();
    float di = g_dinv[node];
    float sl = di * di;
    uint2 sv = xw[node * 32 + lane];
    float2 s0 = __half22float2(*(__half2*)&sv.x);
    float2 s1 = __half22float2(*(__half2*)&sv.y);
    float4 acc = make_float4(s0.x * sl, s0.y * sl, s1.x * sl, s1.y * sl);
    int p    = g_rowptr[node];
    int pend = g_rowptr[node + 1];
    for (int base = p; base < pend; base += 32) {
        int cnt = pend - base;
        if (cnt > 32) cnt = 32;
        int2 rec = make_int2(0, 0);
        if (base + lane < pend) rec = g_csr_sn[base + lane];
        int j = 0;
        // 4-wide: four independent gathers in flight per iteration
        for (; j + 4 <= cnt; j += 4) {
            int sa = __shfl_sync(0xffffffff, rec.x, j);
            int sb = __shfl_sync(0xffffffff, rec.x, j + 1);
            int sc = __shfl_sync(0xffffffff, rec.x, j + 2);
            int sd = __shfl_sync(0xffffffff, rec.x, j + 3);
            float na = __int_as_float(__shfl_sync(0xffffffff, rec.y, j));
            float nb = __int_as_float(__shfl_sync(0xffffffff, rec.y, j + 1));
            float nc = __int_as_float(__shfl_sync(0xffffffff, rec.y, j + 2));
            float nd = __int_as_float(__shfl_sync(0xffffffff, rec.y, j + 3));
            uint2 va = xw[sa * 32 + lane];
            uint2 vb = xw[sb * 32 + lane];
            uint2 vc = xw[sc * 32 + lane];
            uint2 vd = xw[sd * 32 + lane];
            float2 a0, a1;
            a0 = __half22float2(*(__half2*)&va.x); a1 = __half22float2(*(__half2*)&va.y);
            acc.x += a0.x * na; acc.y += a0.y * na; acc.z += a1.x * na; acc.w += a1.y * na;
            a0 = __half22float2(*(__half2*)&vb.x); a1 = __half22float2(*(__half2*)&vb.y);
            acc.x += a0.x * nb; acc.y += a0.y * nb; acc.z += a1.x * nb; acc.w += a1.y * nb;
            a0 = __half22float2(*(__half2*)&vc.x); a1 = __half22float2(*(__half2*)&vc.y);
            acc.x += a0.x * nc; acc.y += a0.y * nc; acc.z += a1.x * nc; acc.w += a1.y * nc;
            a0 = __half22float2(*(__half2*)&vd.x); a1 = __half22float2(*(__half2*)&vd.y);
            acc.x += a0.x * nd; acc.y += a0.y * nd; acc.z += a1.x * nd; acc.w += a1.y * nd;
        }
        for (; j < cnt; j++) {
            int s    = __shfl_sync(0xffffffff, rec.x, j);
            float nm = __int_as_float(__shfl_sync(0xffffffff, rec.y, j));
            uint2 uv = xw[s * 32 + lane];
            float2 u0 = __half22float2(*(__half2*)&uv.x);
            float2 u1 = __half22float2(*(__half2*)&uv.y);
            acc.x += u0.x * nm; acc.y += u0.y * nm;
            acc.z += u1.x * nm; acc.w += u1.y * nm;
        }
    }
    float4 b = ((const float4*)bias)[lane];
    acc.x = fmaxf(acc.x + b.x, 0.f);
    acc.y = fmaxf(acc.y + b.y, 0.f);
    acc.z = fmaxf(acc.z + b.z, 0.f);
    acc.w = fmaxf(acc.w + b.w, 0.f);
    uint2 o;
    *(__half2*)&o.x = __floats2half2_rn(acc.x, acc.y);
    *(__half2*)&o.y = __floats2half2_rn(acc.z, acc.w);
    outh[node * 32 + lane] = o;
}

// ---------------- edge MLP: batched CSR records, 2-wide MLP ----------------
__global__ void edge_kernel(const uint2* __restrict__ Av, const uint2* __restrict__ Bv,
                            const float* __restrict__ Wm2, const float* __restrict__ bm2,
                            float* __restrict__ out) {
    pdl_trigger();
    int node = (blockIdx.x * blockDim.x + threadIdx.x) >> 5;
    int lane = threadIdx.x & 31;
    if (node >= N_NODES) return;
    pdl_wait();
    int p    = g_rowptr[node];
    int pend = g_rowptr[node + 1];
    if (p == pend) return;
    uint2 bv = Bv[node * 32 + lane];
    float2 b0 = __half22float2(*(__half2*)&bv.x);
    float2 b1 = __half22float2(*(__half2*)&bv.y);
    float4 w = ((const float4*)Wm2)[lane];
    float bm = bm2[0];
    for (int base = p; base < pend; base += 32) {
        int cnt = pend - base;
        if (cnt > 32) cnt = 32;
        int2 rec = make_int2(0, 0);
        if (base + lane < pend) rec = g_csr_se[base + lane];
        int j = 0;
        // 2-wide: two A-gathers in flight, two interleaved reductions
        for (; j + 2 <= cnt; j += 2) {
            int sa  = __shfl_sync(0xffffffff, rec.x, j);
            int sb  = __shfl_sync(0xffffffff, rec.x, j + 1);
            int ea  = __shfl_sync(0xffffffff, rec.y, j);
            int eb  = __shfl_sync(0xffffffff, rec.y, j + 1);
            uint2 va = Av[sa * 32 + lane];
            uint2 vb = Av[sb * 32 + lane];
            float2 a0 = __half22float2(*(__half2*)&va.x);
            float2 a1 = __half22float2(*(__half2*)&va.y);
            float2 c0 = __half22float2(*(__half2*)&vb.x);
            float2 c1 = __half22float2(*(__half2*)&vb.y);
            float suma = fmaxf(a0.x + b0.x, 0.f) * w.x
                       + fmaxf(a0.y + b0.y, 0.f) * w.y
                       + fmaxf(a1.x + b1.x, 0.f) * w.z
                       + fmaxf(a1.y + b1.y, 0.f) * w.w;
            float sumb = fmaxf(c0.x + b0.x, 0.f) * w.x
                       + fmaxf(c0.y + b0.y, 0.f) * w.y
                       + fmaxf(c1.x + b1.x, 0.f) * w.z
                       + fmaxf(c1.y + b1.y, 0.f) * w.w;
            #pragma unroll
            for (int off = 16; off > 0; off >>= 1) {
                suma += __shfl_down_sync(0xffffffff, suma, off);
                sumb += __shfl_down_sync(0xffffffff, sumb, off);
            }
            if (lane == 0) {
                out[ea] = suma + bm;
                out[eb] = sumb + bm;
            }
        }
        for (; j < cnt; j++) {
            int s   = __shfl_sync(0xffffffff, rec.x, j);
            int eid = __shfl_sync(0xffffffff, rec.y, j);
            uint2 av = Av[s * 32 + lane];
            float2 a0 = __half22float2(*(__half2*)&av.x);
            float2 a1 = __half22float2(*(__half2*)&av.y);
            float sum = fmaxf(a0.x + b0.x, 0.f) * w.x
                      + fmaxf(a0.y + b0.y, 0.f) * w.y
                      + fmaxf(a1.x + b1.x, 0.f) * w.z
                      + fmaxf(a1.y + b1.y, 0.f) * w.w;
            #pragma unroll
            for (int off = 16; off > 0; off >>= 1)
                sum += __shfl_down_sync(0xffffffff, sum, off);
            if (lane == 0) out[eid] = sum + bm;
        }
    }
}

// ---------------- launch ----------------
static void launch_pdl(const void* fn, dim3 grid, dim3 block, size_t smem,
                       cudaStream_t st, void** args) {
    cudaLaunchConfig_t cfg = {};
    cfg.gridDim = grid; cfg.blockDim = block;
    cfg.dynamicSmemBytes = smem; cfg.stream = st;
    cudaLaunchAttribute attr[1];
    attr[0].id = cudaLaunchAttributeProgrammaticStreamSerialization;
    attr[0].val.programmaticStreamSerializationAllowed = 1;
    cfg.attrs = attr; cfg.numAttrs = 1;
    cudaLaunchKernelExC(&cfg, fn, args);
}

extern "C" void kernel_launch(void* const* d_in, const int* in_sizes, int n_in,
                              void* d_out, int out_size) {
    const float* x      = (const float*)d_in[0];
    const int*   eidx   = (const int*)d_in[1];
    const float* W_in   = (const float*)d_in[2];
    const float* b_in   = (const float*)d_in[3];
    const float* W1     = (const float*)d_in[4];
    const float* b1     = (const float*)d_in[5];
    const float* W2     = (const float*)d_in[6];
    const float* b2     = (const float*)d_in[7];
    const float* Wm1    = (const float*)d_in[8];
    const float* bm1    = (const float*)d_in[9];
    const float* Wm2    = (const float*)d_in[10];
    const float* bm2    = (const float*)d_in[11];
    float* out = (float*)d_out;

    const int* src = eidx;
    const int* dst = eidx + N_EDGES;

    float *buf0f, *buf1f, *buf2f, *buf3f;
    __half *wtin, *wt1, *wt2, *wtm1a, *wtm1b;
    cudaGetSymbolAddress((void**)&buf0f, g_buf0);
    cudaGetSymbolAddress((void**)&buf1f, g_buf1);
    cudaGetSymbolAddress((void**)&buf2f, g_buf2);
    cudaGetSymbolAddress((void**)&buf3f, g_buf3);
    cudaGetSymbolAddress((void**)&wtin, g_wt_in);
    cudaGetSymbolAddress((void**)&wt1, g_wt1);
    cudaGetSymbolAddress((void**)&wt2, g_wt2);
    cudaGetSymbolAddress((void**)&wtm1a, g_wtm1a);
    cudaGetSymbolAddress((void**)&wtm1b, g_wtm1b);

    __half* xh   = (__half*)buf3f;
    __half* xw1h = (__half*)buf0f;
    __half* h1h  = (__half*)buf0f + HALF_OFF;
    __half* xw2h = (__half*)buf1f;
    __half* h2h  = (__half*)buf1f + HALF_OFF;
    __half* Ah   = (__half*)buf2f;
    __half* Bh   = (__half*)buf2f + HALF_OFF;

    static cudaStream_t s2 = nullptr;
    static cudaEvent_t evF = nullptr, evJ = nullptr;
    if (!s2) {
        cudaStreamCreateWithFlags(&s2, cudaStreamNonBlocking);
        cudaEventCreateWithFlags(&evF, cudaEventDisableTiming);
        cudaEventCreateWithFlags(&evJ, cudaEventDisableTiming);
    }

    const int SMEM  = 4 * BUF_BYTES;
    const int SMEMF = 4 * BUF_BYTES + H0_BYTES;
    cudaFuncSetAttribute(gemm_f16_kernel,   cudaFuncAttributeMaxDynamicSharedMemorySize, SMEM);
    cudaFuncSetAttribute(gemm_fused_kernel, cudaFuncAttributeMaxDynamicSharedMemorySize, SMEMF);

    const int TPB = 256;
    dim3 nodeGrid((N_NODES + TPB - 1) / TPB);
    dim3 edgeGrid((N_EDGES + TPB - 1) / TPB);
    dim3 gemmGrid((N_NODES + 127) / 128, 1);
    dim3 gemmGrid2((N_NODES + 127) / 128, 2);
    dim3 warpNodeGrid((N_NODES * 32 + TPB - 1) / TPB);
    dim3 tpb(TPB, 1, 1);

    // ---- fork: CSR build on s2, concurrent with prep + fused GEMM ----
    cudaEventRecord(evF, 0);
    cudaStreamWaitEvent(s2, evF, 0);

    zero_deg_kernel<<<nodeGrid, TPB, 0, s2>>>();
    hist_kernel<<<edgeGrid, TPB, 0, s2>>>(dst);
    scan1_kernel<<<SCAN_BLOCKS, SCAN_TPB, 0, s2>>>();
    scan2_kernel<<<1, 32, 0, s2>>>();
    scan3_kernel<<<SCAN_BLOCKS, SCAN_TPB, 0, s2>>>();
    fill_kernel<<<edgeGrid, TPB, 0, s2>>>(src, dst);
    cudaEventRecord(evJ, s2);

    // main stream: prep (x cvt + all weight transposes) in ONE launch
    prep_kernel<<<CVT_BLOCKS + 48 + 4 * 64, TPB>>>(x, (__half2*)xh, W_in, W1, W2, Wm1,
                                                   wtin, wt1, wt2, wtm1a, wtm1b);

    // xw1 = relu(x@W_in+b_in) @ W1 (fused) — PDL after prep
    {
        static int M = N_NODES;
        void* a[] = {(void*)&xh, (void*)&wtin, (void*)&b_in, (void*)&wt1,
                     (void*)&xw1h, (void*)&M};
        launch_pdl((const void*)gemm_fused_kernel, gemmGrid, tpb, SMEMF, 0, a);
    }

    // ---- join before first aggregation (no PDL across the event) ----
    cudaStreamWaitEvent(0, evJ, 0);

    // h1 = relu(agg(xw1) + b1) — normal launch (has event dependency)
    agg_kernel<<<warpNodeGrid, TPB>>>((const uint2*)xw1h, b1, (uint2*)h1h);

    // xw2 = h1 @ W2 — PDL after agg1
    {
        static const __half* nW1 = nullptr; static const float* nB1 = nullptr;
        static __half* nC1 = nullptr; static int M = N_NODES; static int relu0 = 0;
        void* a[] = {(void*)&h1h, (void*)&wt2, (void*)&nB1, (void*)&xw2h,
                     (void*)&nW1, (void*)&nB1, (void*)&nC1, (void*)&M, (void*)&relu0};
        launch_pdl((const void*)gemm_f16_kernel, gemmGrid, tpb, SMEM, 0, a);
    }

    // h2 = relu(agg(xw2) + b2) — PDL after gemm2
    {
        static const uint2* in2; static const float* bb; static uint2* oo;
        in2 = (const uint2*)xw2h; bb = b2; oo = (uint2*)h2h;
        void* a[] = {(void*)&in2, (void*)&bb, (void*)&oo};
        launch_pdl((const void*)agg_kernel, warpNodeGrid, tpb, 0, 0, a);
    }

    // A = h2 @ Wm1a + bm1 ; B = h2 @ Wm1b — PDL after agg2
    {
        static int M = N_NODES; static int relu0 = 0;
        static const float* nullBias = nullptr;
        void* a[] = {(void*)&h2h, (void*)&wtm1a, (void*)&bm1, (void*)&Ah,
                     (void*)&wtm1b, (void*)&nullBias, (void*)&Bh, (void*)&M, (void*)&relu0};
        launch_pdl((const void*)gemm_f16_kernel, gemmGrid2, tpb, SMEM, 0, a);
    }

    // logits per edge — PDL after gemmAB
    {
        static const uint2* av; static const uint2* bv2;
        av = (const uint2*)Ah; bv2 = (const uint2*)Bh;
        void* a[] = {(void*)&av, (void*)&bv2, (void*)&Wm2, (void*)&bm2, (void*)&out};
        launch_pdl((const void*)edge_kernel, warpNodeGrid, tpb, 0, 0, a);
    }
}